// round 1
// baseline (speedup 1.0000x reference)
#include <cuda_runtime.h>
#include <cstdint>

#define BATCH   4
#define SEQ     2048
#define DMODEL  1024
#define NHEADS  16
#define HDIM    64
#define BHEADS  (BATCH * NHEADS)        // 64
#define ROWS    (BATCH * SEQ)           // 8192

// Scratch (device globals: allocation-free per harness rules)
__device__ float g_qkv[3u * BHEADS * SEQ * HDIM];   // [which][b][h][s][e]
__device__ float g_ctx[(size_t)ROWS * DMODEL];      // [b*s][h*e]

// ---------------------------------------------------------------------------
// GEMM: C = A (MxK, row-major) * B^T (B is NxK row-major).
// M=8192, N=1024, K=1024. 128x128 block tile, BK=8, 256 threads, 8x8 per thread.
// MODE 1: A = x, B selected by blockIdx.z from {Wq,Wk,Wv}, scatter into g_qkv.
// MODE 0: A = g_ctx, B = B0 (Wo), C = Cout plain row-major.
// ---------------------------------------------------------------------------
template <int MODE>
__global__ __launch_bounds__(256, 2)
void gemm_kernel(const float* __restrict__ A,
                 const float* __restrict__ B0,
                 const float* __restrict__ B1,
                 const float* __restrict__ B2,
                 float* __restrict__ Cout)
{
    __shared__ __align__(16) float As[2][8][128];
    __shared__ __align__(16) float Bs[2][8][128];

    const float* Bmat;
    const float* Amat;
    if (MODE == 1) {
        Amat = A;
        Bmat = (blockIdx.z == 0) ? B0 : (blockIdx.z == 1 ? B1 : B2);
    } else {
        Amat = g_ctx;
        Bmat = B0;
    }

    const int tid  = threadIdx.x;
    const int brow = blockIdx.y * 128;
    const int bcol = blockIdx.x * 128;

    const int lrow = tid >> 1;           // 0..127
    const int lk   = (tid & 1) * 4;      // 0 or 4
    const int ty   = tid >> 4;           // 0..15
    const int tx   = tid & 15;           // 0..15
    const int rowg = ty * 8;
    const int colg = tx * 8;

    const float* Ap = Amat + (size_t)(brow + lrow) * DMODEL + lk;
    const float* Bp = Bmat + (size_t)(bcol + lrow) * DMODEL + lk;

    float acc[8][8];
#pragma unroll
    for (int i = 0; i < 8; i++)
#pragma unroll
        for (int j = 0; j < 8; j++) acc[i][j] = 0.0f;

    float4 a4 = *(const float4*)(Ap);
    float4 b4 = *(const float4*)(Bp);

    int cur = 0;
    for (int k0 = 0; k0 < DMODEL; k0 += 8) {
        As[cur][lk + 0][lrow] = a4.x;
        As[cur][lk + 1][lrow] = a4.y;
        As[cur][lk + 2][lrow] = a4.z;
        As[cur][lk + 3][lrow] = a4.w;
        Bs[cur][lk + 0][lrow] = b4.x;
        Bs[cur][lk + 1][lrow] = b4.y;
        Bs[cur][lk + 2][lrow] = b4.z;
        Bs[cur][lk + 3][lrow] = b4.w;
        __syncthreads();

        if (k0 + 8 < DMODEL) {
            a4 = *(const float4*)(Ap + k0 + 8);
            b4 = *(const float4*)(Bp + k0 + 8);
        }

#pragma unroll
        for (int kk = 0; kk < 8; kk++) {
            float a[8], bb[8];
            *(float4*)(a)      = *(const float4*)&As[cur][kk][rowg];
            *(float4*)(a + 4)  = *(const float4*)&As[cur][kk][rowg + 4];
            *(float4*)(bb)     = *(const float4*)&Bs[cur][kk][colg];
            *(float4*)(bb + 4) = *(const float4*)&Bs[cur][kk][colg + 4];
#pragma unroll
            for (int i = 0; i < 8; i++)
#pragma unroll
                for (int j = 0; j < 8; j++)
                    acc[i][j] += a[i] * bb[j];
        }
        cur ^= 1;
    }

    if (MODE == 1) {
        float* out = g_qkv + (size_t)blockIdx.z * (BHEADS * SEQ * HDIM);
#pragma unroll
        for (int i = 0; i < 8; i++) {
            const int r = brow + rowg + i;
            const int b = r >> 11;          // r / SEQ
            const int s = r & (SEQ - 1);
#pragma unroll
            for (int j4 = 0; j4 < 8; j4 += 4) {
                const int c = bcol + colg + j4;
                const int h = c >> 6;
                const int e = c & 63;
                float4 v = make_float4(acc[i][j4], acc[i][j4 + 1],
                                       acc[i][j4 + 2], acc[i][j4 + 3]);
                *(float4*)(out + ((size_t)(b * NHEADS + h) * SEQ + s) * HDIM + e) = v;
            }
        }
    } else {
#pragma unroll
        for (int i = 0; i < 8; i++) {
            const int r = brow + rowg + i;
#pragma unroll
            for (int j4 = 0; j4 < 8; j4 += 4) {
                float4 v = make_float4(acc[i][j4], acc[i][j4 + 1],
                                       acc[i][j4 + 2], acc[i][j4 + 3]);
                *(float4*)(Cout + (size_t)r * DMODEL + bcol + colg + j4) = v;
            }
        }
    }
}

// ---------------------------------------------------------------------------
// Flash attention (causal). One block = 64 queries of one (b,h).
// 256 threads as 16x16; each thread: 4 rows x 4 cols.
// Smem: Qt[e][r], Kt[e][c] (e-major for float4 access), Vs[c][d], Ps[r][c].
// ---------------------------------------------------------------------------
__global__ __launch_bounds__(256, 3)
void flash_kernel()
{
    extern __shared__ float sm[];
    float* Qt = sm;               // 64*64
    float* Kt = sm + 4096;
    float* Vs = sm + 8192;
    float* Ps = sm + 12288;

    const int tid = threadIdx.x;
    const int bh  = blockIdx.y;
    const int b   = bh >> 4;
    const int h   = bh & 15;
    const int qi  = (int)gridDim.x - 1 - (int)blockIdx.x;  // big tiles launch first

    const float* Qg = g_qkv + (size_t)bh * (SEQ * HDIM);
    const float* Kg = g_qkv + (size_t)(BHEADS + bh) * (SEQ * HDIM);
    const float* Vg = g_qkv + (size_t)(2 * BHEADS + bh) * (SEQ * HDIM);

    const int lr = tid >> 2;            // 0..63
    const int le = (tid & 3) * 16;      // 0,16,32,48

    // Load Q tile, transposed to Qt[e][r]
    {
        const float* src = Qg + (size_t)(qi * 64 + lr) * HDIM + le;
#pragma unroll
        for (int i = 0; i < 4; i++) {
            float4 v = *(const float4*)(src + 4 * i);
            const int e = le + 4 * i;
            Qt[(e + 0) * 64 + lr] = v.x;
            Qt[(e + 1) * 64 + lr] = v.y;
            Qt[(e + 2) * 64 + lr] = v.z;
            Qt[(e + 3) * 64 + lr] = v.w;
        }
    }

    const int ty = tid >> 4, tx = tid & 15;
    const int r0 = ty * 4, c0 = tx * 4;

    float m[4], l[4], o[4][4];
#pragma unroll
    for (int i = 0; i < 4; i++) {
        m[i] = -1e30f; l[i] = 0.0f;
#pragma unroll
        for (int j = 0; j < 4; j++) o[i][j] = 0.0f;
    }

    for (int kt = 0; kt <= qi; kt++) {
        __syncthreads();   // everyone done reading Kt/Vs/Ps from previous iter
        // Load K tile transposed, V tile direct
        {
            const float* ks = Kg + (size_t)(kt * 64 + lr) * HDIM + le;
            const float* vs = Vg + (size_t)(kt * 64 + lr) * HDIM + le;
#pragma unroll
            for (int i = 0; i < 4; i++) {
                float4 kv = *(const float4*)(ks + 4 * i);
                const int e = le + 4 * i;
                Kt[(e + 0) * 64 + lr] = kv.x;
                Kt[(e + 1) * 64 + lr] = kv.y;
                Kt[(e + 2) * 64 + lr] = kv.z;
                Kt[(e + 3) * 64 + lr] = kv.w;
                *(float4*)(Vs + lr * 64 + le + 4 * i) = *(const float4*)(vs + 4 * i);
            }
        }
        __syncthreads();

        // S = Q K^T on this tile
        float s[4][4];
#pragma unroll
        for (int i = 0; i < 4; i++)
#pragma unroll
            for (int j = 0; j < 4; j++) s[i][j] = 0.0f;

#pragma unroll 8
        for (int e = 0; e < 64; e++) {
            float4 a = *(const float4*)(Qt + e * 64 + r0);
            float4 q = *(const float4*)(Kt + e * 64 + c0);
            float av[4] = {a.x, a.y, a.z, a.w};
            float qv[4] = {q.x, q.y, q.z, q.w};
#pragma unroll
            for (int i = 0; i < 4; i++)
#pragma unroll
                for (int j = 0; j < 4; j++)
                    s[i][j] += av[i] * qv[j];
        }

        const float scale = 0.125f;   // 1/sqrt(64)
        if (kt == qi) {
#pragma unroll
            for (int i = 0; i < 4; i++)
#pragma unroll
                for (int j = 0; j < 4; j++)
                    s[i][j] = (c0 + j <= r0 + i) ? s[i][j] * scale : -1e30f;
        } else {
#pragma unroll
            for (int i = 0; i < 4; i++)
#pragma unroll
                for (int j = 0; j < 4; j++)
                    s[i][j] *= scale;
        }

        // Online softmax (row reductions over the 16 tx lanes)
#pragma unroll
        for (int i = 0; i < 4; i++) {
            float rm = fmaxf(fmaxf(s[i][0], s[i][1]), fmaxf(s[i][2], s[i][3]));
#pragma unroll
            for (int off = 1; off < 16; off <<= 1)
                rm = fmaxf(rm, __shfl_xor_sync(0xffffffffu, rm, off));
            const float mn = fmaxf(m[i], rm);
            const float al = __expf(m[i] - mn);
            float rs = 0.0f;
#pragma unroll
            for (int j = 0; j < 4; j++) {
                s[i][j] = __expf(s[i][j] - mn);
                rs += s[i][j];
            }
#pragma unroll
            for (int off = 1; off < 16; off <<= 1)
                rs += __shfl_xor_sync(0xffffffffu, rs, off);
            l[i] = l[i] * al + rs;
            m[i] = mn;
#pragma unroll
            for (int j = 0; j < 4; j++) o[i][j] *= al;
        }

        // Stage P
#pragma unroll
        for (int i = 0; i < 4; i++)
            *(float4*)(Ps + (r0 + i) * 64 + c0) =
                make_float4(s[i][0], s[i][1], s[i][2], s[i][3]);
        __syncthreads();

        // O += P V
#pragma unroll 8
        for (int c = 0; c < 64; c++) {
            float4 bv = *(const float4*)(Vs + c * 64 + c0);
            const float a0 = Ps[(r0 + 0) * 64 + c];
            const float a1 = Ps[(r0 + 1) * 64 + c];
            const float a2 = Ps[(r0 + 2) * 64 + c];
            const float a3 = Ps[(r0 + 3) * 64 + c];
            o[0][0] += a0 * bv.x; o[0][1] += a0 * bv.y; o[0][2] += a0 * bv.z; o[0][3] += a0 * bv.w;
            o[1][0] += a1 * bv.x; o[1][1] += a1 * bv.y; o[1][2] += a1 * bv.z; o[1][3] += a1 * bv.w;
            o[2][0] += a2 * bv.x; o[2][1] += a2 * bv.y; o[2][2] += a2 * bv.z; o[2][3] += a2 * bv.w;
            o[3][0] += a3 * bv.x; o[3][1] += a3 * bv.y; o[3][2] += a3 * bv.z; o[3][3] += a3 * bv.w;
        }
    }

    // Write context: g_ctx[(b*SEQ + q) * DMODEL + h*HDIM + d]
#pragma unroll
    for (int i = 0; i < 4; i++) {
        const float inv = 1.0f / l[i];
        float4 v = make_float4(o[i][0] * inv, o[i][1] * inv,
                               o[i][2] * inv, o[i][3] * inv);
        *(float4*)(g_ctx + ((size_t)b * SEQ + qi * 64 + r0 + i) * DMODEL
                   + h * HDIM + c0) = v;
    }
}

// ---------------------------------------------------------------------------
extern "C" void kernel_launch(void* const* d_in, const int* in_sizes, int n_in,
                              void* d_out, int out_size)
{
    const float* x  = (const float*)d_in[0];
    const float* Wq = (const float*)d_in[1];
    const float* Wk = (const float*)d_in[2];
    const float* Wv = (const float*)d_in[3];
    const float* Wo = (const float*)d_in[4];
    float* out = (float*)d_out;

    cudaFuncSetAttribute(flash_kernel,
                         cudaFuncAttributeMaxDynamicSharedMemorySize, 65536);

    // 1) QKV projections (z = which matrix)
    dim3 g1(DMODEL / 128, ROWS / 128, 3);
    gemm_kernel<1><<<g1, 256>>>(x, Wq, Wk, Wv, nullptr);

    // 2) Causal flash attention
    dim3 g2(SEQ / 64, BHEADS);
    flash_kernel<<<g2, 256, 65536>>>();

    // 3) Output projection
    dim3 g3(DMODEL / 128, ROWS / 128, 1);
    gemm_kernel<0><<<g3, 256>>>(nullptr, Wo, nullptr, nullptr, out);
}

// round 3
// speedup vs baseline: 1.2293x; 1.2293x over previous
#include <cuda_runtime.h>
#include <cstdint>

#define BATCH   4
#define SEQ     2048
#define DMODEL  1024
#define NHEADS  16
#define HDIM    64
#define BHEADS  (BATCH * NHEADS)        // 64
#define ROWS    (BATCH * SEQ)           // 8192

// Scratch (device globals: allocation-free per harness rules)
__device__ float g_qkv[3u * BHEADS * SEQ * HDIM];   // [which][b][h][s][e]
__device__ float g_ctx[(size_t)ROWS * DMODEL];      // [b*s][h*e]

// ---------------------------------------------------------------------------
// Helpers: tf32 convert, mma.sync, cp.async
// ---------------------------------------------------------------------------
__device__ __forceinline__ uint32_t f2tf32(float x) {
    uint32_t r;
    asm("cvt.rna.tf32.f32 %0, %1;" : "=r"(r) : "f"(x));
    return r;
}

__device__ __forceinline__ void mma_tf32(float* c,
                                         uint32_t a0, uint32_t a1, uint32_t a2, uint32_t a3,
                                         uint32_t b0, uint32_t b1) {
    asm volatile(
        "mma.sync.aligned.m16n8k8.row.col.f32.tf32.tf32.f32 "
        "{%0,%1,%2,%3}, {%4,%5,%6,%7}, {%8,%9}, {%0,%1,%2,%3};\n"
        : "+f"(c[0]), "+f"(c[1]), "+f"(c[2]), "+f"(c[3])
        : "r"(a0), "r"(a1), "r"(a2), "r"(a3), "r"(b0), "r"(b1));
}

__device__ __forceinline__ void cp16(uint32_t smem_dst, const void* gmem_src) {
    asm volatile("cp.async.cg.shared.global [%0], [%1], 16;\n"
                 :: "r"(smem_dst), "l"(gmem_src));
}
__device__ __forceinline__ void cp_commit() {
    asm volatile("cp.async.commit_group;\n");
}
template <int N>
__device__ __forceinline__ void cp_wait() {
    asm volatile("cp.async.wait_group %0;\n" :: "n"(N));
}

// ---------------------------------------------------------------------------
// Tensor-core GEMM (3xTF32): C = A (MxK row-major) * B^T (B is NxK row-major)
// M=8192, N=1024, K=1024. Block 128x128, BK=32, 256 threads (8 warps),
// warp tile 32x64 (2 m16-tiles x 8 n8-tiles), mma.m16n8k8.tf32.
// 3xTF32 split: a*b ~= ah*bh + ah*bl + al*bh  (error ~ fp32).
// MODE 1: A = x, B from {Wq,Wk,Wv} by blockIdx.z, scatter to g_qkv.
// MODE 0: A = g_ctx, B = B0 (Wo), C = Cout row-major.
// ---------------------------------------------------------------------------
#define ASTR 36          // padded row stride (floats): conflict-free frags+staging
#define TILE_FLOATS (128 * ASTR)

template <int MODE>
__global__ __launch_bounds__(256)
void gemm_tc(const float* __restrict__ A,
             const float* __restrict__ B0,
             const float* __restrict__ B1,
             const float* __restrict__ B2,
             float* __restrict__ Cout)
{
    extern __shared__ float sm[];
    float* As = sm;                    // [2][128][ASTR]
    float* Bs = sm + 2 * TILE_FLOATS;  // [2][128][ASTR]

    const float* Amat;
    const float* Bmat;
    if (MODE == 1) {
        Amat = A;
        Bmat = (blockIdx.z == 0) ? B0 : (blockIdx.z == 1 ? B1 : B2);
    } else {
        Amat = g_ctx;
        Bmat = B0;
    }

    const int tid  = threadIdx.x;
    const int lane = tid & 31;
    const int wid  = tid >> 5;
    const int wm   = wid >> 1;          // 0..3 -> m offset wm*32
    const int wn   = wid & 1;           // 0..1 -> n offset wn*64
    const int gID  = lane >> 2;         // 0..7
    const int tg   = lane & 3;          // 0..3

    const int brow = blockIdx.y * 128;
    const int bcol = blockIdx.x * 128;

    // staging: thread -> (srow, scol); 4 chunks of 32 rows
    const int srow = tid >> 3;          // 0..31
    const int scol = (tid & 7) * 4;     // 0..28

    // Base pointers at the thread's OWN row (srow included ONCE).
    const float* Ag = Amat + (size_t)(brow + srow) * DMODEL + scol;
    const float* Bg = Bmat + (size_t)(bcol + srow) * DMODEL + scol;

    uint32_t as_u32 = (uint32_t)__cvta_generic_to_shared(As);
    uint32_t bs_u32 = (uint32_t)__cvta_generic_to_shared(Bs);

    auto stage = [&](int buf, int k0) {
        const uint32_t abase = as_u32 + (uint32_t)(buf * TILE_FLOATS) * 4u;
        const uint32_t bbase = bs_u32 + (uint32_t)(buf * TILE_FLOATS) * 4u;
#pragma unroll
        for (int i = 0; i < 4; i++) {
            const int r = srow + 32 * i;                       // smem row
            const size_t goff = (size_t)(32 * i) * DMODEL + k0; // gmem delta (srow already in base)
            cp16(abase + (uint32_t)(r * ASTR + scol) * 4u, Ag + goff);
            cp16(bbase + (uint32_t)(r * ASTR + scol) * 4u, Bg + goff);
        }
    };

    float acc[2][8][4];
#pragma unroll
    for (int mt = 0; mt < 2; mt++)
#pragma unroll
        for (int nt = 0; nt < 8; nt++)
#pragma unroll
            for (int i = 0; i < 4; i++) acc[mt][nt][i] = 0.0f;

    stage(0, 0);
    cp_commit();

    for (int kt = 0; kt < DMODEL / 32; kt++) {
        if (kt + 1 < DMODEL / 32) {
            stage((kt + 1) & 1, (kt + 1) * 32);
            cp_commit();
            cp_wait<1>();
        } else {
            cp_wait<0>();
        }
        __syncthreads();

        const float* Ab = As + (kt & 1) * TILE_FLOATS;
        const float* Bb = Bs + (kt & 1) * TILE_FLOATS;

#pragma unroll
        for (int ks = 0; ks < 4; ks++) {
            const int k = ks * 8;

            // A fragments (hi/lo) for both m16 tiles
            uint32_t ah[2][4], al[2][4];
#pragma unroll
            for (int mt = 0; mt < 2; mt++) {
                const int r0 = wm * 32 + mt * 16 + gID;
                float x0 = Ab[(r0)     * ASTR + k + tg];
                float x1 = Ab[(r0 + 8) * ASTR + k + tg];
                float x2 = Ab[(r0)     * ASTR + k + tg + 4];
                float x3 = Ab[(r0 + 8) * ASTR + k + tg + 4];
                ah[mt][0] = f2tf32(x0); al[mt][0] = f2tf32(x0 - __uint_as_float(ah[mt][0]));
                ah[mt][1] = f2tf32(x1); al[mt][1] = f2tf32(x1 - __uint_as_float(ah[mt][1]));
                ah[mt][2] = f2tf32(x2); al[mt][2] = f2tf32(x2 - __uint_as_float(ah[mt][2]));
                ah[mt][3] = f2tf32(x3); al[mt][3] = f2tf32(x3 - __uint_as_float(ah[mt][3]));
            }

#pragma unroll
            for (int nt = 0; nt < 8; nt++) {
                const int c0 = wn * 64 + nt * 8 + gID;
                float y0 = Bb[c0 * ASTR + k + tg];
                float y1 = Bb[c0 * ASTR + k + tg + 4];
                uint32_t bh0 = f2tf32(y0), bh1 = f2tf32(y1);
                uint32_t bl0 = f2tf32(y0 - __uint_as_float(bh0));
                uint32_t bl1 = f2tf32(y1 - __uint_as_float(bh1));
#pragma unroll
                for (int mt = 0; mt < 2; mt++) {
                    mma_tf32(acc[mt][nt], ah[mt][0], ah[mt][1], ah[mt][2], ah[mt][3], bh0, bh1);
                    mma_tf32(acc[mt][nt], ah[mt][0], ah[mt][1], ah[mt][2], ah[mt][3], bl0, bl1);
                    mma_tf32(acc[mt][nt], al[mt][0], al[mt][1], al[mt][2], al[mt][3], bh0, bh1);
                }
            }
        }
        __syncthreads();
    }

    // Epilogue
    if (MODE == 1) {
        float* out = g_qkv + (size_t)blockIdx.z * (BHEADS * SEQ * HDIM);
#pragma unroll
        for (int mt = 0; mt < 2; mt++) {
            const int rbase = brow + wm * 32 + mt * 16 + gID;
#pragma unroll
            for (int nt = 0; nt < 8; nt++) {
                const int col = bcol + wn * 64 + nt * 8 + tg * 2;
                const int h = col >> 6;
                const int e = col & 63;
#pragma unroll
                for (int half = 0; half < 2; half++) {
                    const int r = rbase + half * 8;
                    const int b = r >> 11;
                    const int s = r & (SEQ - 1);
                    float2 v = make_float2(acc[mt][nt][half * 2], acc[mt][nt][half * 2 + 1]);
                    *(float2*)(out + ((size_t)(b * NHEADS + h) * SEQ + s) * HDIM + e) = v;
                }
            }
        }
    } else {
#pragma unroll
        for (int mt = 0; mt < 2; mt++) {
            const int rbase = brow + wm * 32 + mt * 16 + gID;
#pragma unroll
            for (int nt = 0; nt < 8; nt++) {
                const int col = bcol + wn * 64 + nt * 8 + tg * 2;
#pragma unroll
                for (int half = 0; half < 2; half++) {
                    const int r = rbase + half * 8;
                    float2 v = make_float2(acc[mt][nt][half * 2], acc[mt][nt][half * 2 + 1]);
                    *(float2*)(Cout + (size_t)r * DMODEL + col) = v;
                }
            }
        }
    }
}

// ---------------------------------------------------------------------------
// Flash attention (causal), unchanged from R1 (passing baseline).
// ---------------------------------------------------------------------------
__global__ __launch_bounds__(256, 3)
void flash_kernel()
{
    extern __shared__ float sm[];
    float* Qt = sm;               // 64*64
    float* Kt = sm + 4096;
    float* Vs = sm + 8192;
    float* Ps = sm + 12288;

    const int tid = threadIdx.x;
    const int bh  = blockIdx.y;
    const int b   = bh >> 4;
    const int h   = bh & 15;
    const int qi  = (int)gridDim.x - 1 - (int)blockIdx.x;  // big tiles launch first

    const float* Qg = g_qkv + (size_t)bh * (SEQ * HDIM);
    const float* Kg = g_qkv + (size_t)(BHEADS + bh) * (SEQ * HDIM);
    const float* Vg = g_qkv + (size_t)(2 * BHEADS + bh) * (SEQ * HDIM);

    const int lr = tid >> 2;            // 0..63
    const int le = (tid & 3) * 16;      // 0,16,32,48

    {
        const float* src = Qg + (size_t)(qi * 64 + lr) * HDIM + le;
#pragma unroll
        for (int i = 0; i < 4; i++) {
            float4 v = *(const float4*)(src + 4 * i);
            const int e = le + 4 * i;
            Qt[(e + 0) * 64 + lr] = v.x;
            Qt[(e + 1) * 64 + lr] = v.y;
            Qt[(e + 2) * 64 + lr] = v.z;
            Qt[(e + 3) * 64 + lr] = v.w;
        }
    }

    const int ty = tid >> 4, tx = tid & 15;
    const int r0 = ty * 4, c0 = tx * 4;

    float m[4], l[4], o[4][4];
#pragma unroll
    for (int i = 0; i < 4; i++) {
        m[i] = -1e30f; l[i] = 0.0f;
#pragma unroll
        for (int j = 0; j < 4; j++) o[i][j] = 0.0f;
    }

    for (int kt = 0; kt <= qi; kt++) {
        __syncthreads();
        {
            const float* ks = Kg + (size_t)(kt * 64 + lr) * HDIM + le;
            const float* vs = Vg + (size_t)(kt * 64 + lr) * HDIM + le;
#pragma unroll
            for (int i = 0; i < 4; i++) {
                float4 kv = *(const float4*)(ks + 4 * i);
                const int e = le + 4 * i;
                Kt[(e + 0) * 64 + lr] = kv.x;
                Kt[(e + 1) * 64 + lr] = kv.y;
                Kt[(e + 2) * 64 + lr] = kv.z;
                Kt[(e + 3) * 64 + lr] = kv.w;
                *(float4*)(Vs + lr * 64 + le + 4 * i) = *(const float4*)(vs + 4 * i);
            }
        }
        __syncthreads();

        float s[4][4];
#pragma unroll
        for (int i = 0; i < 4; i++)
#pragma unroll
            for (int j = 0; j < 4; j++) s[i][j] = 0.0f;

#pragma unroll 8
        for (int e = 0; e < 64; e++) {
            float4 a = *(const float4*)(Qt + e * 64 + r0);
            float4 q = *(const float4*)(Kt + e * 64 + c0);
            float av[4] = {a.x, a.y, a.z, a.w};
            float qv[4] = {q.x, q.y, q.z, q.w};
#pragma unroll
            for (int i = 0; i < 4; i++)
#pragma unroll
                for (int j = 0; j < 4; j++)
                    s[i][j] += av[i] * qv[j];
        }

        const float scale = 0.125f;
        if (kt == qi) {
#pragma unroll
            for (int i = 0; i < 4; i++)
#pragma unroll
                for (int j = 0; j < 4; j++)
                    s[i][j] = (c0 + j <= r0 + i) ? s[i][j] * scale : -1e30f;
        } else {
#pragma unroll
            for (int i = 0; i < 4; i++)
#pragma unroll
                for (int j = 0; j < 4; j++)
                    s[i][j] *= scale;
        }

#pragma unroll
        for (int i = 0; i < 4; i++) {
            float rm = fmaxf(fmaxf(s[i][0], s[i][1]), fmaxf(s[i][2], s[i][3]));
#pragma unroll
            for (int off = 1; off < 16; off <<= 1)
                rm = fmaxf(rm, __shfl_xor_sync(0xffffffffu, rm, off));
            const float mn = fmaxf(m[i], rm);
            const float al = __expf(m[i] - mn);
            float rs = 0.0f;
#pragma unroll
            for (int j = 0; j < 4; j++) {
                s[i][j] = __expf(s[i][j] - mn);
                rs += s[i][j];
            }
#pragma unroll
            for (int off = 1; off < 16; off <<= 1)
                rs += __shfl_xor_sync(0xffffffffu, rs, off);
            l[i] = l[i] * al + rs;
            m[i] = mn;
#pragma unroll
            for (int j = 0; j < 4; j++) o[i][j] *= al;
        }

#pragma unroll
        for (int i = 0; i < 4; i++)
            *(float4*)(Ps + (r0 + i) * 64 + c0) =
                make_float4(s[i][0], s[i][1], s[i][2], s[i][3]);
        __syncthreads();

#pragma unroll 8
        for (int c = 0; c < 64; c++) {
            float4 bv = *(const float4*)(Vs + c * 64 + c0);
            const float a0 = Ps[(r0 + 0) * 64 + c];
            const float a1 = Ps[(r0 + 1) * 64 + c];
            const float a2 = Ps[(r0 + 2) * 64 + c];
            const float a3 = Ps[(r0 + 3) * 64 + c];
            o[0][0] += a0 * bv.x; o[0][1] += a0 * bv.y; o[0][2] += a0 * bv.z; o[0][3] += a0 * bv.w;
            o[1][0] += a1 * bv.x; o[1][1] += a1 * bv.y; o[1][2] += a1 * bv.z; o[1][3] += a1 * bv.w;
            o[2][0] += a2 * bv.x; o[2][1] += a2 * bv.y; o[2][2] += a2 * bv.z; o[2][3] += a2 * bv.w;
            o[3][0] += a3 * bv.x; o[3][1] += a3 * bv.y; o[3][2] += a3 * bv.z; o[3][3] += a3 * bv.w;
        }
    }

#pragma unroll
    for (int i = 0; i < 4; i++) {
        const float inv = 1.0f / l[i];
        float4 v = make_float4(o[i][0] * inv, o[i][1] * inv,
                               o[i][2] * inv, o[i][3] * inv);
        *(float4*)(g_ctx + ((size_t)b * SEQ + qi * 64 + r0 + i) * DMODEL
                   + h * HDIM + c0) = v;
    }
}

// ---------------------------------------------------------------------------
extern "C" void kernel_launch(void* const* d_in, const int* in_sizes, int n_in,
                              void* d_out, int out_size)
{
    const float* x  = (const float*)d_in[0];
    const float* Wq = (const float*)d_in[1];
    const float* Wk = (const float*)d_in[2];
    const float* Wv = (const float*)d_in[3];
    const float* Wo = (const float*)d_in[4];
    float* out = (float*)d_out;

    const int gemm_smem = 4 * TILE_FLOATS * 4;   // 73728 bytes

    cudaFuncSetAttribute(gemm_tc<1>,
                         cudaFuncAttributeMaxDynamicSharedMemorySize, gemm_smem);
    cudaFuncSetAttribute(gemm_tc<0>,
                         cudaFuncAttributeMaxDynamicSharedMemorySize, gemm_smem);
    cudaFuncSetAttribute(flash_kernel,
                         cudaFuncAttributeMaxDynamicSharedMemorySize, 65536);

    // 1) QKV projections (z = which matrix)
    dim3 g1(DMODEL / 128, ROWS / 128, 3);
    gemm_tc<1><<<g1, 256, gemm_smem>>>(x, Wq, Wk, Wv, nullptr);

    // 2) Causal flash attention
    dim3 g2(SEQ / 64, BHEADS);
    flash_kernel<<<g2, 256, 65536>>>();

    // 3) Output projection
    dim3 g3(DMODEL / 128, ROWS / 128, 1);
    gemm_tc<0><<<g3, 256, gemm_smem>>>(nullptr, Wo, nullptr, nullptr, out);
}

// round 4
// speedup vs baseline: 1.3227x; 1.0760x over previous
#include <cuda_runtime.h>
#include <cstdint>

#define BATCH   4
#define SEQ     2048
#define DMODEL  1024
#define NHEADS  16
#define HDIM    64
#define BHEADS  (BATCH * NHEADS)        // 64
#define ROWS    (BATCH * SEQ)           // 8192

// Scratch (device globals: allocation-free per harness rules)
__device__ float g_qkv[3u * BHEADS * SEQ * HDIM];   // [which][b][h][s][e]
__device__ float g_ctx[(size_t)ROWS * DMODEL];      // [b*s][h*e]

// ---------------------------------------------------------------------------
// Helpers
// ---------------------------------------------------------------------------
__device__ __forceinline__ uint32_t f2tf32(float x) {
    uint32_t r;
    asm("cvt.rna.tf32.f32 %0, %1;" : "=r"(r) : "f"(x));
    return r;
}

__device__ __forceinline__ void mma_tf32(float* c,
                                         uint32_t a0, uint32_t a1, uint32_t a2, uint32_t a3,
                                         uint32_t b0, uint32_t b1) {
    asm volatile(
        "mma.sync.aligned.m16n8k8.row.col.f32.tf32.tf32.f32 "
        "{%0,%1,%2,%3}, {%4,%5,%6,%7}, {%8,%9}, {%0,%1,%2,%3};\n"
        : "+f"(c[0]), "+f"(c[1]), "+f"(c[2]), "+f"(c[3])
        : "r"(a0), "r"(a1), "r"(a2), "r"(a3), "r"(b0), "r"(b1));
}

__device__ __forceinline__ void cp16(uint32_t smem_dst, const void* gmem_src) {
    asm volatile("cp.async.cg.shared.global [%0], [%1], 16;\n"
                 :: "r"(smem_dst), "l"(gmem_src));
}
__device__ __forceinline__ void cp_commit() {
    asm volatile("cp.async.commit_group;\n");
}
template <int N>
__device__ __forceinline__ void cp_wait() {
    asm volatile("cp.async.wait_group %0;\n" :: "n"(N));
}

// split x into hi (tf32 bits as float) and lo
__device__ __forceinline__ void split_tf32(float x, float& hi, float& lo) {
    uint32_t h = f2tf32(x);
    hi = __uint_as_float(h);
    lo = __uint_as_float(f2tf32(x - hi));
}

// ---------------------------------------------------------------------------
// Tensor-core GEMM (3xTF32) — unchanged from R3 (passing).
// ---------------------------------------------------------------------------
#define ASTR 36
#define TILE_FLOATS (128 * ASTR)

template <int MODE>
__global__ __launch_bounds__(256)
void gemm_tc(const float* __restrict__ A,
             const float* __restrict__ B0,
             const float* __restrict__ B1,
             const float* __restrict__ B2,
             float* __restrict__ Cout)
{
    extern __shared__ float sm[];
    float* As = sm;
    float* Bs = sm + 2 * TILE_FLOATS;

    const float* Amat;
    const float* Bmat;
    if (MODE == 1) {
        Amat = A;
        Bmat = (blockIdx.z == 0) ? B0 : (blockIdx.z == 1 ? B1 : B2);
    } else {
        Amat = g_ctx;
        Bmat = B0;
    }

    const int tid  = threadIdx.x;
    const int lane = tid & 31;
    const int wid  = tid >> 5;
    const int wm   = wid >> 1;
    const int wn   = wid & 1;
    const int gID  = lane >> 2;
    const int tg   = lane & 3;

    const int brow = blockIdx.y * 128;
    const int bcol = blockIdx.x * 128;

    const int srow = tid >> 3;
    const int scol = (tid & 7) * 4;

    const float* Ag = Amat + (size_t)(brow + srow) * DMODEL + scol;
    const float* Bg = Bmat + (size_t)(bcol + srow) * DMODEL + scol;

    uint32_t as_u32 = (uint32_t)__cvta_generic_to_shared(As);
    uint32_t bs_u32 = (uint32_t)__cvta_generic_to_shared(Bs);

    auto stage = [&](int buf, int k0) {
        const uint32_t abase = as_u32 + (uint32_t)(buf * TILE_FLOATS) * 4u;
        const uint32_t bbase = bs_u32 + (uint32_t)(buf * TILE_FLOATS) * 4u;
#pragma unroll
        for (int i = 0; i < 4; i++) {
            const int r = srow + 32 * i;
            const size_t goff = (size_t)(32 * i) * DMODEL + k0;
            cp16(abase + (uint32_t)(r * ASTR + scol) * 4u, Ag + goff);
            cp16(bbase + (uint32_t)(r * ASTR + scol) * 4u, Bg + goff);
        }
    };

    float acc[2][8][4];
#pragma unroll
    for (int mt = 0; mt < 2; mt++)
#pragma unroll
        for (int nt = 0; nt < 8; nt++)
#pragma unroll
            for (int i = 0; i < 4; i++) acc[mt][nt][i] = 0.0f;

    stage(0, 0);
    cp_commit();

    for (int kt = 0; kt < DMODEL / 32; kt++) {
        if (kt + 1 < DMODEL / 32) {
            stage((kt + 1) & 1, (kt + 1) * 32);
            cp_commit();
            cp_wait<1>();
        } else {
            cp_wait<0>();
        }
        __syncthreads();

        const float* Ab = As + (kt & 1) * TILE_FLOATS;
        const float* Bb = Bs + (kt & 1) * TILE_FLOATS;

#pragma unroll
        for (int ks = 0; ks < 4; ks++) {
            const int k = ks * 8;

            uint32_t ah[2][4], al[2][4];
#pragma unroll
            for (int mt = 0; mt < 2; mt++) {
                const int r0 = wm * 32 + mt * 16 + gID;
                float x0 = Ab[(r0)     * ASTR + k + tg];
                float x1 = Ab[(r0 + 8) * ASTR + k + tg];
                float x2 = Ab[(r0)     * ASTR + k + tg + 4];
                float x3 = Ab[(r0 + 8) * ASTR + k + tg + 4];
                ah[mt][0] = f2tf32(x0); al[mt][0] = f2tf32(x0 - __uint_as_float(ah[mt][0]));
                ah[mt][1] = f2tf32(x1); al[mt][1] = f2tf32(x1 - __uint_as_float(ah[mt][1]));
                ah[mt][2] = f2tf32(x2); al[mt][2] = f2tf32(x2 - __uint_as_float(ah[mt][2]));
                ah[mt][3] = f2tf32(x3); al[mt][3] = f2tf32(x3 - __uint_as_float(ah[mt][3]));
            }

#pragma unroll
            for (int nt = 0; nt < 8; nt++) {
                const int c0 = wn * 64 + nt * 8 + gID;
                float y0 = Bb[c0 * ASTR + k + tg];
                float y1 = Bb[c0 * ASTR + k + tg + 4];
                uint32_t bh0 = f2tf32(y0), bh1 = f2tf32(y1);
                uint32_t bl0 = f2tf32(y0 - __uint_as_float(bh0));
                uint32_t bl1 = f2tf32(y1 - __uint_as_float(bh1));
#pragma unroll
                for (int mt = 0; mt < 2; mt++) {
                    mma_tf32(acc[mt][nt], ah[mt][0], ah[mt][1], ah[mt][2], ah[mt][3], bh0, bh1);
                    mma_tf32(acc[mt][nt], ah[mt][0], ah[mt][1], ah[mt][2], ah[mt][3], bl0, bl1);
                    mma_tf32(acc[mt][nt], al[mt][0], al[mt][1], al[mt][2], al[mt][3], bh0, bh1);
                }
            }
        }
        __syncthreads();
    }

    if (MODE == 1) {
        float* out = g_qkv + (size_t)blockIdx.z * (BHEADS * SEQ * HDIM);
#pragma unroll
        for (int mt = 0; mt < 2; mt++) {
            const int rbase = brow + wm * 32 + mt * 16 + gID;
#pragma unroll
            for (int nt = 0; nt < 8; nt++) {
                const int col = bcol + wn * 64 + nt * 8 + tg * 2;
                const int h = col >> 6;
                const int e = col & 63;
#pragma unroll
                for (int half = 0; half < 2; half++) {
                    const int r = rbase + half * 8;
                    const int b = r >> 11;
                    const int s = r & (SEQ - 1);
                    float2 v = make_float2(acc[mt][nt][half * 2], acc[mt][nt][half * 2 + 1]);
                    *(float2*)(out + ((size_t)(b * NHEADS + h) * SEQ + s) * HDIM + e) = v;
                }
            }
        }
    } else {
#pragma unroll
        for (int mt = 0; mt < 2; mt++) {
            const int rbase = brow + wm * 32 + mt * 16 + gID;
#pragma unroll
            for (int nt = 0; nt < 8; nt++) {
                const int col = bcol + wn * 64 + nt * 8 + tg * 2;
#pragma unroll
                for (int half = 0; half < 2; half++) {
                    const int r = rbase + half * 8;
                    float2 v = make_float2(acc[mt][nt][half * 2], acc[mt][nt][half * 2 + 1]);
                    *(float2*)(Cout + (size_t)r * DMODEL + col) = v;
                }
            }
        }
    }
}

// ---------------------------------------------------------------------------
// Tensor-core flash attention (causal, 3xTF32).
// Block = 128 queries of one (b,h). 256 threads, 8 warps; warp w owns rows
// w*16..w*16+15. K-tiles of 64 keys. Q/K/P/V pre-split hi/lo in smem (stride
// 68 -> conflict-free fragment loads). V staged transposed for B fragments.
// ---------------------------------------------------------------------------
#define BQ   128
#define BKT  64
#define SSTR 68
#define FL_SMEM_FLOATS (2*BQ*SSTR + 2*BKT*SSTR + 2*BKT*SSTR + 2*BQ*SSTR)

__global__ __launch_bounds__(256)
void flash_tc()
{
    extern __shared__ float sm[];
    float* Qhi = sm;                      // [128][68]
    float* Qlo = Qhi + BQ * SSTR;
    float* Khi = Qlo + BQ * SSTR;         // [64][68]  (rows = keys, cols = e)
    float* Klo = Khi + BKT * SSTR;
    float* Vhi = Klo + BKT * SSTR;        // [64][68]  (rows = e, cols = keys)
    float* Vlo = Vhi + BKT * SSTR;
    float* Phi = Vlo + BKT * SSTR;        // [128][68]
    float* Plo = Phi + BQ * SSTR;

    const int tid  = threadIdx.x;
    const int lane = tid & 31;
    const int wid  = tid >> 5;
    const int gID  = lane >> 2;
    const int tg   = lane & 3;

    const int bh    = blockIdx.y;
    const int b     = bh >> 4;
    const int h     = bh & 15;
    const int qi    = (int)gridDim.x - 1 - (int)blockIdx.x;   // big work first
    const int qbase = qi * BQ;

    const float* Qg = g_qkv + (size_t)bh * (SEQ * HDIM);
    const float* Kg = g_qkv + (size_t)(BHEADS + bh) * (SEQ * HDIM);
    const float* Vg = g_qkv + (size_t)(2 * BHEADS + bh) * (SEQ * HDIM);

    // ---- Load + split Q tile: thread -> row tid>>1, 32-col half ----
    {
        const int r  = tid >> 1;
        const int c0 = (tid & 1) * 32;
        const float* src = Qg + (size_t)(qbase + r) * HDIM + c0;
#pragma unroll
        for (int i = 0; i < 8; i++) {
            float4 v = *(const float4*)(src + 4 * i);
            float h0, l0_, h1, l1_, h2, l2_, h3, l3_;
            split_tf32(v.x, h0, l0_); split_tf32(v.y, h1, l1_);
            split_tf32(v.z, h2, l2_); split_tf32(v.w, h3, l3_);
            const int off = r * SSTR + c0 + 4 * i;
            *(float4*)(Qhi + off) = make_float4(h0, h1, h2, h3);
            *(float4*)(Qlo + off) = make_float4(l0_, l1_, l2_, l3_);
        }
    }

    const int rloc = wid * 16 + gID;     // local row (first of the pair)

    float m0 = -1e30f, m1 = -1e30f, l0 = 0.0f, l1 = 0.0f;
    float oacc[8][4];
#pragma unroll
    for (int nt = 0; nt < 8; nt++)
#pragma unroll
        for (int i = 0; i < 4; i++) oacc[nt][i] = 0.0f;

    const int nkt = 2 * qi + 2;
    for (int kt = 0; kt < nkt; kt++) {
        __syncthreads();   // previous iteration's K/V/Q reads complete

        // ---- Stage K (split) and V (split + transpose) ----
        {
            const int r  = tid >> 2;            // 0..63 key row
            const int c0 = (tid & 3) * 16;      // e col base
            const float* ks = Kg + (size_t)(kt * BKT + r) * HDIM + c0;
            const float* vs = Vg + (size_t)(kt * BKT + r) * HDIM + c0;
#pragma unroll
            for (int i = 0; i < 4; i++) {
                float4 kv = *(const float4*)(ks + 4 * i);
                float h0, lo0, h1, lo1, h2, lo2, h3, lo3;
                split_tf32(kv.x, h0, lo0); split_tf32(kv.y, h1, lo1);
                split_tf32(kv.z, h2, lo2); split_tf32(kv.w, h3, lo3);
                const int off = r * SSTR + c0 + 4 * i;
                *(float4*)(Khi + off) = make_float4(h0, h1, h2, h3);
                *(float4*)(Klo + off) = make_float4(lo0, lo1, lo2, lo3);

                float4 vv = *(const float4*)(vs + 4 * i);
                split_tf32(vv.x, h0, lo0); split_tf32(vv.y, h1, lo1);
                split_tf32(vv.z, h2, lo2); split_tf32(vv.w, h3, lo3);
                const int e = c0 + 4 * i;
                Vhi[(e + 0) * SSTR + r] = h0;  Vlo[(e + 0) * SSTR + r] = lo0;
                Vhi[(e + 1) * SSTR + r] = h1;  Vlo[(e + 1) * SSTR + r] = lo1;
                Vhi[(e + 2) * SSTR + r] = h2;  Vlo[(e + 2) * SSTR + r] = lo2;
                Vhi[(e + 3) * SSTR + r] = h3;  Vlo[(e + 3) * SSTR + r] = lo3;
            }
        }
        __syncthreads();

        // ---- S = Q K^T (3xTF32) ----
        float sacc[8][4];
#pragma unroll
        for (int nt = 0; nt < 8; nt++)
#pragma unroll
            for (int i = 0; i < 4; i++) sacc[nt][i] = 0.0f;

#pragma unroll
        for (int ks = 0; ks < 8; ks++) {
            const int k = ks * 8;
            const int a0 = rloc * SSTR + k + tg;
            const int a1 = (rloc + 8) * SSTR + k + tg;
            uint32_t ah0 = __float_as_uint(Qhi[a0]);
            uint32_t ah1 = __float_as_uint(Qhi[a1]);
            uint32_t ah2 = __float_as_uint(Qhi[a0 + 4]);
            uint32_t ah3 = __float_as_uint(Qhi[a1 + 4]);
            uint32_t al0 = __float_as_uint(Qlo[a0]);
            uint32_t al1 = __float_as_uint(Qlo[a1]);
            uint32_t al2 = __float_as_uint(Qlo[a0 + 4]);
            uint32_t al3 = __float_as_uint(Qlo[a1 + 4]);
#pragma unroll
            for (int nt = 0; nt < 8; nt++) {
                const int bb = (nt * 8 + gID) * SSTR + k + tg;
                uint32_t bh0 = __float_as_uint(Khi[bb]);
                uint32_t bh1 = __float_as_uint(Khi[bb + 4]);
                uint32_t bl0 = __float_as_uint(Klo[bb]);
                uint32_t bl1 = __float_as_uint(Klo[bb + 4]);
                mma_tf32(sacc[nt], ah0, ah1, ah2, ah3, bh0, bh1);
                mma_tf32(sacc[nt], ah0, ah1, ah2, ah3, bl0, bl1);
                mma_tf32(sacc[nt], al0, al1, al2, al3, bh0, bh1);
            }
        }

        // ---- Online softmax in fragment layout ----
        const bool diag = (kt >= 2 * qi);
        const float scale = 0.125f;

#pragma unroll
        for (int half = 0; half < 2; half++) {
            const int rg = qbase + rloc + half * 8;      // global row
            float& m = half ? m1 : m0;
            float& l = half ? l1 : l0;

            float mx = -1e30f;
#pragma unroll
            for (int nt = 0; nt < 8; nt++) {
#pragma unroll
                for (int j = 0; j < 2; j++) {
                    float s = sacc[nt][half * 2 + j] * scale;
                    if (diag) {
                        const int cg = kt * BKT + nt * 8 + tg * 2 + j;
                        if (cg > rg) s = -1e30f;
                    }
                    sacc[nt][half * 2 + j] = s;
                    mx = fmaxf(mx, s);
                }
            }
            mx = fmaxf(mx, __shfl_xor_sync(0xffffffffu, mx, 1));
            mx = fmaxf(mx, __shfl_xor_sync(0xffffffffu, mx, 2));

            const float mn = fmaxf(m, mx);
            const float alpha = __expf(m - mn);
            float rs = 0.0f;
#pragma unroll
            for (int nt = 0; nt < 8; nt++) {
                float p0 = __expf(sacc[nt][half * 2 + 0] - mn);
                float p1 = __expf(sacc[nt][half * 2 + 1] - mn);
                rs += p0 + p1;
                float h0, lo0, h1, lo1;
                split_tf32(p0, h0, lo0);
                split_tf32(p1, h1, lo1);
                const int off = (rloc + half * 8) * SSTR + nt * 8 + tg * 2;
                *(float2*)(Phi + off) = make_float2(h0, h1);
                *(float2*)(Plo + off) = make_float2(lo0, lo1);
            }
            rs += __shfl_xor_sync(0xffffffffu, rs, 1);
            rs += __shfl_xor_sync(0xffffffffu, rs, 2);
            l = l * alpha + rs;
            m = mn;
#pragma unroll
            for (int nt = 0; nt < 8; nt++) {
                oacc[nt][half * 2 + 0] *= alpha;
                oacc[nt][half * 2 + 1] *= alpha;
            }
        }
        __syncwarp();   // P visible within warp (each warp reads only its rows)

        // ---- O += P V (3xTF32) ----
#pragma unroll
        for (int ks = 0; ks < 8; ks++) {
            const int k = ks * 8;
            const int a0 = rloc * SSTR + k + tg;
            const int a1 = (rloc + 8) * SSTR + k + tg;
            uint32_t ah0 = __float_as_uint(Phi[a0]);
            uint32_t ah1 = __float_as_uint(Phi[a1]);
            uint32_t ah2 = __float_as_uint(Phi[a0 + 4]);
            uint32_t ah3 = __float_as_uint(Phi[a1 + 4]);
            uint32_t al0 = __float_as_uint(Plo[a0]);
            uint32_t al1 = __float_as_uint(Plo[a1]);
            uint32_t al2 = __float_as_uint(Plo[a0 + 4]);
            uint32_t al3 = __float_as_uint(Plo[a1 + 4]);
#pragma unroll
            for (int nt = 0; nt < 8; nt++) {
                const int bb = (nt * 8 + gID) * SSTR + k + tg;
                uint32_t bh0 = __float_as_uint(Vhi[bb]);
                uint32_t bh1 = __float_as_uint(Vhi[bb + 4]);
                uint32_t bl0 = __float_as_uint(Vlo[bb]);
                uint32_t bl1 = __float_as_uint(Vlo[bb + 4]);
                mma_tf32(oacc[nt], ah0, ah1, ah2, ah3, bh0, bh1);
                mma_tf32(oacc[nt], ah0, ah1, ah2, ah3, bl0, bl1);
                mma_tf32(oacc[nt], al0, al1, al2, al3, bh0, bh1);
            }
        }
    }

    // ---- Epilogue: O /= l, write to g_ctx ----
    const float inv0 = 1.0f / l0;
    const float inv1 = 1.0f / l1;
#pragma unroll
    for (int half = 0; half < 2; half++) {
        const float inv = half ? inv1 : inv0;
        const int rg = qbase + rloc + half * 8;
        float* dst = g_ctx + ((size_t)b * SEQ + rg) * DMODEL + h * HDIM;
#pragma unroll
        for (int nt = 0; nt < 8; nt++) {
            float2 v = make_float2(oacc[nt][half * 2 + 0] * inv,
                                   oacc[nt][half * 2 + 1] * inv);
            *(float2*)(dst + nt * 8 + tg * 2) = v;
        }
    }
}

// ---------------------------------------------------------------------------
extern "C" void kernel_launch(void* const* d_in, const int* in_sizes, int n_in,
                              void* d_out, int out_size)
{
    const float* x  = (const float*)d_in[0];
    const float* Wq = (const float*)d_in[1];
    const float* Wk = (const float*)d_in[2];
    const float* Wv = (const float*)d_in[3];
    const float* Wo = (const float*)d_in[4];
    float* out = (float*)d_out;

    const int gemm_smem  = 4 * TILE_FLOATS * 4;        // 73728 B
    const int flash_smem = FL_SMEM_FLOATS * 4;         // 208896 B

    cudaFuncSetAttribute(gemm_tc<1>,
                         cudaFuncAttributeMaxDynamicSharedMemorySize, gemm_smem);
    cudaFuncSetAttribute(gemm_tc<0>,
                         cudaFuncAttributeMaxDynamicSharedMemorySize, gemm_smem);
    cudaFuncSetAttribute(flash_tc,
                         cudaFuncAttributeMaxDynamicSharedMemorySize, flash_smem);

    // 1) QKV projections
    dim3 g1(DMODEL / 128, ROWS / 128, 3);
    gemm_tc<1><<<g1, 256, gemm_smem>>>(x, Wq, Wk, Wv, nullptr);

    // 2) Causal flash attention (tensor cores)
    dim3 g2(SEQ / BQ, BHEADS);
    flash_tc<<<g2, 256, flash_smem>>>();

    // 3) Output projection
    dim3 g3(DMODEL / 128, ROWS / 128, 1);
    gemm_tc<0><<<g3, 256, gemm_smem>>>(nullptr, Wo, nullptr, nullptr, out);
}

// round 5
// speedup vs baseline: 2.1000x; 1.5876x over previous
#include <cuda_runtime.h>
#include <cuda_bf16.h>
#include <cstdint>

#define BATCH   4
#define SEQ     2048
#define DMODEL  1024
#define NHEADS  16
#define HDIM    64
#define BHEADS  (BATCH * NHEADS)        // 64
#define ROWS    (BATCH * SEQ)           // 8192

// ---------------------------------------------------------------------------
// Device-global scratch (bf16 hi/lo planes everywhere)
// ---------------------------------------------------------------------------
__device__ __nv_bfloat16 g_xh[(size_t)ROWS * DMODEL];
__device__ __nv_bfloat16 g_xl[(size_t)ROWS * DMODEL];
__device__ __nv_bfloat16 g_wh[4u * DMODEL * DMODEL];   // q,k,v,o  (n x k row-major)
__device__ __nv_bfloat16 g_wl[4u * DMODEL * DMODEL];
__device__ __nv_bfloat16 g_qkvh[3u * BHEADS * SEQ * HDIM];  // [which][bh][s][e]
__device__ __nv_bfloat16 g_qkvl[3u * BHEADS * SEQ * HDIM];
__device__ __nv_bfloat16 g_ctxh[(size_t)ROWS * DMODEL];
__device__ __nv_bfloat16 g_ctxl[(size_t)ROWS * DMODEL];

// ---------------------------------------------------------------------------
// Helpers
// ---------------------------------------------------------------------------
__device__ __forceinline__ void mma_bf16(float* c,
                                         uint32_t a0, uint32_t a1, uint32_t a2, uint32_t a3,
                                         uint32_t b0, uint32_t b1) {
    asm volatile(
        "mma.sync.aligned.m16n8k16.row.col.f32.bf16.bf16.f32 "
        "{%0,%1,%2,%3}, {%4,%5,%6,%7}, {%8,%9}, {%0,%1,%2,%3};\n"
        : "+f"(c[0]), "+f"(c[1]), "+f"(c[2]), "+f"(c[3])
        : "r"(a0), "r"(a1), "r"(a2), "r"(a3), "r"(b0), "r"(b1));
}

__device__ __forceinline__ void cp16(uint32_t smem_dst, const void* gmem_src) {
    asm volatile("cp.async.cg.shared.global [%0], [%1], 16;\n"
                 :: "r"(smem_dst), "l"(gmem_src));
}
__device__ __forceinline__ void cp_commit() {
    asm volatile("cp.async.commit_group;\n");
}
template <int N>
__device__ __forceinline__ void cp_wait() {
    asm volatile("cp.async.wait_group %0;\n" :: "n"(N));
}

// split float -> bf16 hi + bf16 lo
__device__ __forceinline__ void split_bf(float x, __nv_bfloat16& h, __nv_bfloat16& l) {
    h = __float2bfloat16(x);
    l = __float2bfloat16(x - __bfloat162float(h));
}
// pack two bf16 (even k in low half) into a 32-bit word
__device__ __forceinline__ uint32_t pack2(__nv_bfloat16 a, __nv_bfloat16 b) {
    return (uint32_t)__bfloat16_as_ushort(a) | ((uint32_t)__bfloat16_as_ushort(b) << 16);
}

// ---------------------------------------------------------------------------
// Pre-split kernel: f32 -> (hi, lo) bf16 planes. n % 4 == 0.
// ---------------------------------------------------------------------------
__global__ void split_kernel(const float* __restrict__ src,
                             __nv_bfloat16* __restrict__ hi,
                             __nv_bfloat16* __restrict__ lo, int n)
{
    int i = (blockIdx.x * blockDim.x + threadIdx.x) * 4;
    if (i >= n) return;
    float4 v = *(const float4*)(src + i);
    __nv_bfloat16 h0, l0, h1, l1, h2, l2, h3, l3;
    split_bf(v.x, h0, l0); split_bf(v.y, h1, l1);
    split_bf(v.z, h2, l2); split_bf(v.w, h3, l3);
    *(uint32_t*)(hi + i)     = pack2(h0, h1);
    *(uint32_t*)(hi + i + 2) = pack2(h2, h3);
    *(uint32_t*)(lo + i)     = pack2(l0, l1);
    *(uint32_t*)(lo + i + 2) = pack2(l2, l3);
}

// ---------------------------------------------------------------------------
// bf16x3 tensor-core GEMM: C = A (MxK rm) * B^T (B NxK rm), M=8192,N=1024,K=1024
// 128x128 block, BK=32, 256 thr (8 warps: 4 wm x 2 wn), warp 32x64,
// mma.m16n8k16. All operands pre-split bf16 planes; zero cvt in loop.
// MODE 1: A = x planes, B = W[z] planes, epilogue split -> g_qkv planes.
// MODE 0: A = ctx planes, B = W[3] (Wo), epilogue f32 -> Cout.
// ---------------------------------------------------------------------------
#define SWG     20                 // words (bf16 pairs) per smem row: 16 data + 4 pad
#define PLANEW  (128 * SWG)        // words per plane
#define GSMEM_W (2 * 4 * PLANEW)   // 2 buffers x 4 planes

template <int MODE>
__global__ __launch_bounds__(256)
void gemm_bf(float* __restrict__ Cout)
{
    extern __shared__ uint32_t smw[];

    const __nv_bfloat16 *Ah, *Al, *Bh, *Bl;
    if (MODE == 1) {
        Ah = g_xh;  Al = g_xl;
        const size_t wo = (size_t)blockIdx.z * DMODEL * DMODEL;
        Bh = g_wh + wo;  Bl = g_wl + wo;
    } else {
        Ah = g_ctxh;  Al = g_ctxl;
        Bh = g_wh + 3u * DMODEL * DMODEL;  Bl = g_wl + 3u * DMODEL * DMODEL;
    }

    const int tid  = threadIdx.x;
    const int lane = tid & 31;
    const int wid  = tid >> 5;
    const int wm   = wid >> 1;
    const int wn   = wid & 1;
    const int gID  = lane >> 2;
    const int tg   = lane & 3;

    const int brow = blockIdx.y * 128;
    const int bcol = blockIdx.x * 128;

    // staging map: thread -> row tid>>1 (0..127), chunk base (tid&1)*2 (+0,1)
    const int srow = tid >> 1;
    const int cb   = (tid & 1) * 2;

    const uint32_t smem0 = (uint32_t)__cvta_generic_to_shared(smw);

    auto stage = [&](int buf, int k0) {
        const uint32_t base = smem0 + (uint32_t)(buf * 4 * PLANEW) * 4u;
        const __nv_bfloat16* gsrc[4] = {
            Ah + (size_t)(brow + srow) * DMODEL + k0,
            Al + (size_t)(brow + srow) * DMODEL + k0,
            Bh + (size_t)(bcol + srow) * DMODEL + k0,
            Bl + (size_t)(bcol + srow) * DMODEL + k0 };
#pragma unroll
        for (int p = 0; p < 4; p++) {
#pragma unroll
            for (int j = 0; j < 2; j++) {
                const int c = cb + j;   // 16B chunk (8 bf16 = 4 words)
                cp16(base + (uint32_t)(p * PLANEW + srow * SWG + c * 4) * 4u,
                     gsrc[p] + c * 8);
            }
        }
    };

    float acc[2][8][4];
#pragma unroll
    for (int mt = 0; mt < 2; mt++)
#pragma unroll
        for (int nt = 0; nt < 8; nt++)
#pragma unroll
            for (int i = 0; i < 4; i++) acc[mt][nt][i] = 0.0f;

    stage(0, 0);
    cp_commit();

    for (int kt = 0; kt < DMODEL / 32; kt++) {
        if (kt + 1 < DMODEL / 32) {
            stage((kt + 1) & 1, (kt + 1) * 32);
            cp_commit();
            cp_wait<1>();
        } else {
            cp_wait<0>();
        }
        __syncthreads();

        const uint32_t* W  = smw + (kt & 1) * 4 * PLANEW;
        const uint32_t* wAh = W;
        const uint32_t* wAl = W + PLANEW;
        const uint32_t* wBh = W + 2 * PLANEW;
        const uint32_t* wBl = W + 3 * PLANEW;

#pragma unroll
        for (int ks = 0; ks < 2; ks++) {
            const int wb = ks * 8;

            uint32_t ah[2][4], al[2][4];
#pragma unroll
            for (int mt = 0; mt < 2; mt++) {
                const int r0 = wm * 32 + mt * 16 + gID;
                ah[mt][0] = wAh[r0 * SWG + wb + tg];
                ah[mt][1] = wAh[(r0 + 8) * SWG + wb + tg];
                ah[mt][2] = wAh[r0 * SWG + wb + tg + 4];
                ah[mt][3] = wAh[(r0 + 8) * SWG + wb + tg + 4];
                al[mt][0] = wAl[r0 * SWG + wb + tg];
                al[mt][1] = wAl[(r0 + 8) * SWG + wb + tg];
                al[mt][2] = wAl[r0 * SWG + wb + tg + 4];
                al[mt][3] = wAl[(r0 + 8) * SWG + wb + tg + 4];
            }

#pragma unroll
            for (int nt = 0; nt < 8; nt++) {
                const int c0 = wn * 64 + nt * 8 + gID;
                uint32_t bh0 = wBh[c0 * SWG + wb + tg];
                uint32_t bh1 = wBh[c0 * SWG + wb + tg + 4];
                uint32_t bl0 = wBl[c0 * SWG + wb + tg];
                uint32_t bl1 = wBl[c0 * SWG + wb + tg + 4];
#pragma unroll
                for (int mt = 0; mt < 2; mt++) {
                    mma_bf16(acc[mt][nt], ah[mt][0], ah[mt][1], ah[mt][2], ah[mt][3], bh0, bh1);
                    mma_bf16(acc[mt][nt], ah[mt][0], ah[mt][1], ah[mt][2], ah[mt][3], bl0, bl1);
                    mma_bf16(acc[mt][nt], al[mt][0], al[mt][1], al[mt][2], al[mt][3], bh0, bh1);
                }
            }
        }
        __syncthreads();
    }

    if (MODE == 1) {
        const size_t zo = (size_t)blockIdx.z * (BHEADS * SEQ * HDIM);
#pragma unroll
        for (int mt = 0; mt < 2; mt++) {
            const int rbase = brow + wm * 32 + mt * 16 + gID;
#pragma unroll
            for (int nt = 0; nt < 8; nt++) {
                const int col = bcol + wn * 64 + nt * 8 + tg * 2;
                const int h = col >> 6;
                const int e = col & 63;
#pragma unroll
                for (int half = 0; half < 2; half++) {
                    const int r = rbase + half * 8;
                    const int b = r >> 11;
                    const int s = r & (SEQ - 1);
                    const size_t o = zo + ((size_t)(b * NHEADS + h) * SEQ + s) * HDIM + e;
                    __nv_bfloat16 h0, l0, h1, l1;
                    split_bf(acc[mt][nt][half * 2 + 0], h0, l0);
                    split_bf(acc[mt][nt][half * 2 + 1], h1, l1);
                    *(uint32_t*)(g_qkvh + o) = pack2(h0, h1);
                    *(uint32_t*)(g_qkvl + o) = pack2(l0, l1);
                }
            }
        }
    } else {
#pragma unroll
        for (int mt = 0; mt < 2; mt++) {
            const int rbase = brow + wm * 32 + mt * 16 + gID;
#pragma unroll
            for (int nt = 0; nt < 8; nt++) {
                const int col = bcol + wn * 64 + nt * 8 + tg * 2;
#pragma unroll
                for (int half = 0; half < 2; half++) {
                    const int r = rbase + half * 8;
                    float2 v = make_float2(acc[mt][nt][half * 2], acc[mt][nt][half * 2 + 1]);
                    *(float2*)(Cout + (size_t)r * DMODEL + col) = v;
                }
            }
        }
    }
}

// ---------------------------------------------------------------------------
// bf16x3 flash attention (causal). Block = 128 queries of one (b,h).
// 256 thr, 8 warps (warp w: rows w*16..+15). K-tiles of 64 keys.
// Q/K staged via cp.async from pre-split planes; V transposed on stage;
// P split-packed once per tile. All fragments: scalar LDS.32 of bf16 pairs.
// ---------------------------------------------------------------------------
#define BQ   128
#define BKT  64
#define SWF  36                    // words per row: 32 data + 4 pad
#define QW   (BQ * SWF)            // 4608
#define KW   (BKT * SWF)           // 2304
#define FSMEM_W (2*QW + 2*KW + 2*KW + 2*QW)   // 27648 words = 110592 B

__global__ __launch_bounds__(256)
void flash_bf()
{
    extern __shared__ uint32_t smw[];
    uint32_t* Qh = smw;
    uint32_t* Ql = Qh + QW;
    uint32_t* Kh = Ql + QW;
    uint32_t* Kl = Kh + KW;
    uint32_t* Vh = Kl + KW;        // V^T: [e][s-pair words]
    uint32_t* Vl = Vh + KW;
    uint32_t* Ph = Vl + KW;
    uint32_t* Pl = Ph + QW;

    const int tid  = threadIdx.x;
    const int lane = tid & 31;
    const int wid  = tid >> 5;
    const int gID  = lane >> 2;
    const int tg   = lane & 3;

    const int bh    = blockIdx.y;
    const int b     = bh >> 4;
    const int h     = bh & 15;
    const int qi    = (int)gridDim.x - 1 - (int)blockIdx.x;
    const int qbase = qi * BQ;

    const __nv_bfloat16* Qhp = g_qkvh + (size_t)bh * (SEQ * HDIM);
    const __nv_bfloat16* Qlp = g_qkvl + (size_t)bh * (SEQ * HDIM);
    const __nv_bfloat16* Khp = g_qkvh + (size_t)(BHEADS + bh) * (SEQ * HDIM);
    const __nv_bfloat16* Klp = g_qkvl + (size_t)(BHEADS + bh) * (SEQ * HDIM);
    const __nv_bfloat16* Vhp = g_qkvh + (size_t)(2 * BHEADS + bh) * (SEQ * HDIM);
    const __nv_bfloat16* Vlp = g_qkvl + (size_t)(2 * BHEADS + bh) * (SEQ * HDIM);

    const uint32_t smem0 = (uint32_t)__cvta_generic_to_shared(smw);
    const uint32_t Qh_b = smem0;
    const uint32_t Ql_b = smem0 + QW * 4u;
    const uint32_t Kh_b = Ql_b + QW * 4u;
    const uint32_t Kl_b = Kh_b + KW * 4u;

    // ---- Q staging (once): row tid>>1, chunks (tid&1)*4 + 0..3 (16B each) ----
    {
        const int r  = tid >> 1;
        const int c0 = (tid & 1) * 4;
        const __nv_bfloat16* sh = Qhp + (size_t)(qbase + r) * HDIM;
        const __nv_bfloat16* sl = Qlp + (size_t)(qbase + r) * HDIM;
#pragma unroll
        for (int j = 0; j < 4; j++) {
            const int c = c0 + j;
            cp16(Qh_b + (uint32_t)(r * SWF + c * 4) * 4u, sh + c * 8);
            cp16(Ql_b + (uint32_t)(r * SWF + c * 4) * 4u, sl + c * 8);
        }
        cp_commit();
    }

    const int rloc = wid * 16 + gID;

    float m0 = -1e30f, m1 = -1e30f, l0 = 0.0f, l1 = 0.0f;
    float oacc[8][4];
#pragma unroll
    for (int nt = 0; nt < 8; nt++)
#pragma unroll
        for (int i = 0; i < 4; i++) oacc[nt][i] = 0.0f;

    const int nkt = 2 * qi + 2;
    for (int kt = 0; kt < nkt; kt++) {
        __syncthreads();   // previous tile's smem reads complete

        // ---- K staging: cp.async ----
        {
            const int r  = tid >> 2;           // 0..63
            const int c0 = (tid & 3) * 2;      // chunks c0, c0+1
            const __nv_bfloat16* sh = Khp + (size_t)(kt * BKT + r) * HDIM;
            const __nv_bfloat16* sl = Klp + (size_t)(kt * BKT + r) * HDIM;
#pragma unroll
            for (int j = 0; j < 2; j++) {
                const int c = c0 + j;
                cp16(Kh_b + (uint32_t)(r * SWF + c * 4) * 4u, sh + c * 8);
                cp16(Kl_b + (uint32_t)(r * SWF + c * 4) * 4u, sl + c * 8);
            }
            cp_commit();
        }

        // ---- V staging with transpose (LDG + scalar halfword STS) ----
        {
            const int r     = tid & 63;            // key row
            const int ebase = (tid >> 6) * 16;     // 16 e-values
            const size_t off = (size_t)(kt * BKT + r) * HDIM + ebase;
            uint4 h0 = *(const uint4*)(Vhp + off);
            uint4 h1 = *(const uint4*)(Vhp + off + 8);
            uint4 q0 = *(const uint4*)(Vlp + off);
            uint4 q1 = *(const uint4*)(Vlp + off + 8);
            uint32_t wh[8] = {h0.x, h0.y, h0.z, h0.w, h1.x, h1.y, h1.z, h1.w};
            uint32_t wl[8] = {q0.x, q0.y, q0.z, q0.w, q1.x, q1.y, q1.z, q1.w};
            uint16_t* vh16 = (uint16_t*)Vh;
            uint16_t* vl16 = (uint16_t*)Vl;
#pragma unroll
            for (int w = 0; w < 8; w++) {
                const int e = ebase + 2 * w;
                vh16[(e    ) * (2 * SWF) + r] = (uint16_t)(wh[w] & 0xffff);
                vh16[(e + 1) * (2 * SWF) + r] = (uint16_t)(wh[w] >> 16);
                vl16[(e    ) * (2 * SWF) + r] = (uint16_t)(wl[w] & 0xffff);
                vl16[(e + 1) * (2 * SWF) + r] = (uint16_t)(wl[w] >> 16);
            }
        }
        cp_wait<0>();
        __syncthreads();

        // ---- S = Q K^T ----
        float sacc[8][4];
#pragma unroll
        for (int nt = 0; nt < 8; nt++)
#pragma unroll
            for (int i = 0; i < 4; i++) sacc[nt][i] = 0.0f;

#pragma unroll
        for (int ks = 0; ks < 4; ks++) {
            const int wb = ks * 8;
            const int a0 = rloc * SWF + wb + tg;
            const int a1 = (rloc + 8) * SWF + wb + tg;
            uint32_t ah0 = Qh[a0], ah1 = Qh[a1], ah2 = Qh[a0 + 4], ah3 = Qh[a1 + 4];
            uint32_t al0 = Ql[a0], al1 = Ql[a1], al2 = Ql[a0 + 4], al3 = Ql[a1 + 4];
#pragma unroll
            for (int nt = 0; nt < 8; nt++) {
                const int bb = (nt * 8 + gID) * SWF + wb + tg;
                uint32_t bh0 = Kh[bb], bh1 = Kh[bb + 4];
                uint32_t bl0 = Kl[bb], bl1 = Kl[bb + 4];
                mma_bf16(sacc[nt], ah0, ah1, ah2, ah3, bh0, bh1);
                mma_bf16(sacc[nt], ah0, ah1, ah2, ah3, bl0, bl1);
                mma_bf16(sacc[nt], al0, al1, al2, al3, bh0, bh1);
            }
        }

        // ---- Online softmax + P split-pack ----
        const bool diag = (kt >= 2 * qi);
        const float scale = 0.125f;

#pragma unroll
        for (int half = 0; half < 2; half++) {
            const int rg = qbase + rloc + half * 8;
            float& m = half ? m1 : m0;
            float& l = half ? l1 : l0;

            float mx = -1e30f;
#pragma unroll
            for (int nt = 0; nt < 8; nt++) {
#pragma unroll
                for (int j = 0; j < 2; j++) {
                    float s = sacc[nt][half * 2 + j] * scale;
                    if (diag) {
                        const int cg = kt * BKT + nt * 8 + tg * 2 + j;
                        if (cg > rg) s = -1e30f;
                    }
                    sacc[nt][half * 2 + j] = s;
                    mx = fmaxf(mx, s);
                }
            }
            mx = fmaxf(mx, __shfl_xor_sync(0xffffffffu, mx, 1));
            mx = fmaxf(mx, __shfl_xor_sync(0xffffffffu, mx, 2));

            const float mn = fmaxf(m, mx);
            const float alpha = __expf(m - mn);
            float rs = 0.0f;
            const int prow = (rloc + half * 8) * SWF;
#pragma unroll
            for (int nt = 0; nt < 8; nt++) {
                float p0 = __expf(sacc[nt][half * 2 + 0] - mn);
                float p1 = __expf(sacc[nt][half * 2 + 1] - mn);
                rs += p0 + p1;
                __nv_bfloat16 h0, lo0, h1, lo1;
                split_bf(p0, h0, lo0);
                split_bf(p1, h1, lo1);
                Ph[prow + nt * 4 + tg] = pack2(h0, h1);
                Pl[prow + nt * 4 + tg] = pack2(lo0, lo1);
            }
            rs += __shfl_xor_sync(0xffffffffu, rs, 1);
            rs += __shfl_xor_sync(0xffffffffu, rs, 2);
            l = l * alpha + rs;
            m = mn;
#pragma unroll
            for (int nt = 0; nt < 8; nt++) {
                oacc[nt][half * 2 + 0] *= alpha;
                oacc[nt][half * 2 + 1] *= alpha;
            }
        }
        __syncwarp();   // each warp reads only its own P rows

        // ---- O += P V ----
#pragma unroll
        for (int ks = 0; ks < 4; ks++) {
            const int wb = ks * 8;
            const int a0 = rloc * SWF + wb + tg;
            const int a1 = (rloc + 8) * SWF + wb + tg;
            uint32_t ah0 = Ph[a0], ah1 = Ph[a1], ah2 = Ph[a0 + 4], ah3 = Ph[a1 + 4];
            uint32_t al0 = Pl[a0], al1 = Pl[a1], al2 = Pl[a0 + 4], al3 = Pl[a1 + 4];
#pragma unroll
            for (int nt = 0; nt < 8; nt++) {
                const int bb = (nt * 8 + gID) * SWF + wb + tg;
                uint32_t bh0 = Vh[bb], bh1 = Vh[bb + 4];
                uint32_t bl0 = Vl[bb], bl1 = Vl[bb + 4];
                mma_bf16(oacc[nt], ah0, ah1, ah2, ah3, bh0, bh1);
                mma_bf16(oacc[nt], ah0, ah1, ah2, ah3, bl0, bl1);
                mma_bf16(oacc[nt], al0, al1, al2, al3, bh0, bh1);
            }
        }
    }

    // ---- Epilogue: normalize, split, write ctx planes ----
    const float inv0 = 1.0f / l0;
    const float inv1 = 1.0f / l1;
#pragma unroll
    for (int half = 0; half < 2; half++) {
        const float inv = half ? inv1 : inv0;
        const int rg = qbase + rloc + half * 8;
        const size_t rowo = ((size_t)b * SEQ + rg) * DMODEL + h * HDIM;
#pragma unroll
        for (int nt = 0; nt < 8; nt++) {
            float v0 = oacc[nt][half * 2 + 0] * inv;
            float v1 = oacc[nt][half * 2 + 1] * inv;
            __nv_bfloat16 h0, lo0, h1, lo1;
            split_bf(v0, h0, lo0);
            split_bf(v1, h1, lo1);
            const size_t o = rowo + nt * 8 + tg * 2;
            *(uint32_t*)(g_ctxh + o) = pack2(h0, h1);
            *(uint32_t*)(g_ctxl + o) = pack2(lo0, lo1);
        }
    }
}

// ---------------------------------------------------------------------------
extern "C" void kernel_launch(void* const* d_in, const int* in_sizes, int n_in,
                              void* d_out, int out_size)
{
    const float* x  = (const float*)d_in[0];
    const float* Wq = (const float*)d_in[1];
    const float* Wk = (const float*)d_in[2];
    const float* Wv = (const float*)d_in[3];
    const float* Wo = (const float*)d_in[4];
    float* out = (float*)d_out;

    const int gsmem = GSMEM_W * 4;     // 81920 B
    const int fsmem = FSMEM_W * 4;     // 110592 B

    cudaFuncSetAttribute(gemm_bf<1>,
                         cudaFuncAttributeMaxDynamicSharedMemorySize, gsmem);
    cudaFuncSetAttribute(gemm_bf<0>,
                         cudaFuncAttributeMaxDynamicSharedMemorySize, gsmem);
    cudaFuncSetAttribute(flash_bf,
                         cudaFuncAttributeMaxDynamicSharedMemorySize, fsmem);

    // 0) pre-split inputs into bf16 hi/lo planes
    __nv_bfloat16 *xh, *xl, *wh, *wl;
    cudaGetSymbolAddress((void**)&xh, g_xh);
    cudaGetSymbolAddress((void**)&xl, g_xl);
    cudaGetSymbolAddress((void**)&wh, g_wh);
    cudaGetSymbolAddress((void**)&wl, g_wl);

    const int nx = ROWS * DMODEL;
    const int nw = DMODEL * DMODEL;
    split_kernel<<<(nx / 4 + 255) / 256, 256>>>(x, xh, xl, nx);
    split_kernel<<<(nw / 4 + 255) / 256, 256>>>(Wq, wh + 0 * (size_t)nw, wl + 0 * (size_t)nw, nw);
    split_kernel<<<(nw / 4 + 255) / 256, 256>>>(Wk, wh + 1 * (size_t)nw, wl + 1 * (size_t)nw, nw);
    split_kernel<<<(nw / 4 + 255) / 256, 256>>>(Wv, wh + 2 * (size_t)nw, wl + 2 * (size_t)nw, nw);
    split_kernel<<<(nw / 4 + 255) / 256, 256>>>(Wo, wh + 3 * (size_t)nw, wl + 3 * (size_t)nw, nw);

    // 1) QKV projections
    dim3 g1(DMODEL / 128, ROWS / 128, 3);
    gemm_bf<1><<<g1, 256, gsmem>>>(nullptr);

    // 2) Causal flash attention
    dim3 g2(SEQ / BQ, BHEADS);
    flash_bf<<<g2, 256, fsmem>>>();

    // 3) Output projection
    dim3 g3(DMODEL / 128, ROWS / 128, 1);
    gemm_bf<0><<<g3, 256, gsmem>>>(out);
}

// round 8
// speedup vs baseline: 2.2339x; 1.0638x over previous
#include <cuda_runtime.h>
#include <cuda_bf16.h>
#include <cstdint>

#define BATCH   4
#define SEQ     2048
#define DMODEL  1024
#define NHEADS  16
#define HDIM    64
#define BHEADS  (BATCH * NHEADS)        // 64
#define ROWS    (BATCH * SEQ)           // 8192

// ---------------------------------------------------------------------------
// Device-global scratch (bf16 hi/lo planes)
// ---------------------------------------------------------------------------
__device__ __nv_bfloat16 g_xh[(size_t)ROWS * DMODEL];
__device__ __nv_bfloat16 g_xl[(size_t)ROWS * DMODEL];
__device__ __nv_bfloat16 g_wh[4u * DMODEL * DMODEL];   // q,k,v,o  (n x k row-major)
__device__ __nv_bfloat16 g_wl[4u * DMODEL * DMODEL];
__device__ __nv_bfloat16 g_qkvh[3u * BHEADS * SEQ * HDIM];  // [which][bh][s][e]
__device__ __nv_bfloat16 g_qkvl[3u * BHEADS * SEQ * HDIM];
__device__ __nv_bfloat16 g_ctxh[(size_t)ROWS * DMODEL];
__device__ __nv_bfloat16 g_ctxl[(size_t)ROWS * DMODEL];

// ---------------------------------------------------------------------------
// Helpers
// ---------------------------------------------------------------------------
__device__ __forceinline__ void mma_bf16(float* c,
                                         uint32_t a0, uint32_t a1, uint32_t a2, uint32_t a3,
                                         uint32_t b0, uint32_t b1) {
    asm volatile(
        "mma.sync.aligned.m16n8k16.row.col.f32.bf16.bf16.f32 "
        "{%0,%1,%2,%3}, {%4,%5,%6,%7}, {%8,%9}, {%0,%1,%2,%3};\n"
        : "+f"(c[0]), "+f"(c[1]), "+f"(c[2]), "+f"(c[3])
        : "r"(a0), "r"(a1), "r"(a2), "r"(a3), "r"(b0), "r"(b1));
}

__device__ __forceinline__ void ldsm4(uint32_t* r, uint32_t addr) {
    asm volatile("ldmatrix.sync.aligned.m8n8.x4.shared.b16 {%0,%1,%2,%3}, [%4];"
                 : "=r"(r[0]), "=r"(r[1]), "=r"(r[2]), "=r"(r[3]) : "r"(addr));
}
__device__ __forceinline__ void ldsm4t(uint32_t* r, uint32_t addr) {
    asm volatile("ldmatrix.sync.aligned.m8n8.x4.trans.shared.b16 {%0,%1,%2,%3}, [%4];"
                 : "=r"(r[0]), "=r"(r[1]), "=r"(r[2]), "=r"(r[3]) : "r"(addr));
}

__device__ __forceinline__ void cp16(uint32_t smem_dst, const void* gmem_src) {
    asm volatile("cp.async.cg.shared.global [%0], [%1], 16;\n"
                 :: "r"(smem_dst), "l"(gmem_src));
}
__device__ __forceinline__ void cp_commit() {
    asm volatile("cp.async.commit_group;\n");
}
template <int N>
__device__ __forceinline__ void cp_wait() {
    asm volatile("cp.async.wait_group %0;\n" :: "n"(N));
}

__device__ __forceinline__ void split_bf(float x, __nv_bfloat16& h, __nv_bfloat16& l) {
    h = __float2bfloat16(x);
    l = __float2bfloat16(x - __bfloat162float(h));
}
__device__ __forceinline__ uint32_t pack2(__nv_bfloat16 a, __nv_bfloat16 b) {
    return (uint32_t)__bfloat16_as_ushort(a) | ((uint32_t)__bfloat16_as_ushort(b) << 16);
}

// ---------------------------------------------------------------------------
// Pre-split kernels
// ---------------------------------------------------------------------------
__global__ void split_kernel(const float* __restrict__ src,
                             __nv_bfloat16* __restrict__ hi,
                             __nv_bfloat16* __restrict__ lo, int n)
{
    int i = (blockIdx.x * blockDim.x + threadIdx.x) * 4;
    if (i >= n) return;
    float4 v = *(const float4*)(src + i);
    __nv_bfloat16 h0, l0, h1, l1, h2, l2, h3, l3;
    split_bf(v.x, h0, l0); split_bf(v.y, h1, l1);
    split_bf(v.z, h2, l2); split_bf(v.w, h3, l3);
    *(uint32_t*)(hi + i)     = pack2(h0, h1);
    *(uint32_t*)(hi + i + 2) = pack2(h2, h3);
    *(uint32_t*)(lo + i)     = pack2(l0, l1);
    *(uint32_t*)(lo + i + 2) = pack2(l2, l3);
}

__global__ void split4_kernel(const float* __restrict__ W0, const float* __restrict__ W1,
                              const float* __restrict__ W2, const float* __restrict__ W3)
{
    const int z = blockIdx.y;
    const float* src = (z == 0) ? W0 : (z == 1) ? W1 : (z == 2) ? W2 : W3;
    const size_t nw = (size_t)DMODEL * DMODEL;
    __nv_bfloat16* hi = g_wh + z * nw;
    __nv_bfloat16* lo = g_wl + z * nw;
    int i = (blockIdx.x * blockDim.x + threadIdx.x) * 4;
    if (i >= (int)nw) return;
    float4 v = *(const float4*)(src + i);
    __nv_bfloat16 h0, l0, h1, l1, h2, l2, h3, l3;
    split_bf(v.x, h0, l0); split_bf(v.y, h1, l1);
    split_bf(v.z, h2, l2); split_bf(v.w, h3, l3);
    *(uint32_t*)(hi + i)     = pack2(h0, h1);
    *(uint32_t*)(hi + i + 2) = pack2(h2, h3);
    *(uint32_t*)(lo + i)     = pack2(l0, l1);
    *(uint32_t*)(lo + i + 2) = pack2(l2, l3);
}

// ---------------------------------------------------------------------------
// bf16x3 legacy-mma GEMM (R5, proven): C = A (MxK rm) * B^T (B NxK rm).
// ---------------------------------------------------------------------------
#define SWG     20
#define PLANEW  (128 * SWG)
#define GSMEM_W (2 * 4 * PLANEW)

template <int MODE>
__global__ __launch_bounds__(256)
void gemm_bf(float* __restrict__ Cout)
{
    extern __shared__ uint32_t smw[];

    const __nv_bfloat16 *Ah, *Al, *Bh, *Bl;
    if (MODE == 1) {
        Ah = g_xh;  Al = g_xl;
        const size_t wo = (size_t)blockIdx.z * DMODEL * DMODEL;
        Bh = g_wh + wo;  Bl = g_wl + wo;
    } else {
        Ah = g_ctxh;  Al = g_ctxl;
        Bh = g_wh + 3u * DMODEL * DMODEL;  Bl = g_wl + 3u * DMODEL * DMODEL;
    }

    const int tid  = threadIdx.x;
    const int lane = tid & 31;
    const int wid  = tid >> 5;
    const int wm   = wid >> 1;
    const int wn   = wid & 1;
    const int gID  = lane >> 2;
    const int tg   = lane & 3;

    const int brow = blockIdx.y * 128;
    const int bcol = blockIdx.x * 128;

    const int srow = tid >> 1;
    const int cb   = (tid & 1) * 2;

    const uint32_t smem0 = (uint32_t)__cvta_generic_to_shared(smw);

    auto stage = [&](int buf, int k0) {
        const uint32_t base = smem0 + (uint32_t)(buf * 4 * PLANEW) * 4u;
        const __nv_bfloat16* gsrc[4] = {
            Ah + (size_t)(brow + srow) * DMODEL + k0,
            Al + (size_t)(brow + srow) * DMODEL + k0,
            Bh + (size_t)(bcol + srow) * DMODEL + k0,
            Bl + (size_t)(bcol + srow) * DMODEL + k0 };
#pragma unroll
        for (int p = 0; p < 4; p++) {
#pragma unroll
            for (int j = 0; j < 2; j++) {
                const int c = cb + j;
                cp16(base + (uint32_t)(p * PLANEW + srow * SWG + c * 4) * 4u,
                     gsrc[p] + c * 8);
            }
        }
    };

    float acc[2][8][4];
#pragma unroll
    for (int mt = 0; mt < 2; mt++)
#pragma unroll
        for (int nt = 0; nt < 8; nt++)
#pragma unroll
            for (int i = 0; i < 4; i++) acc[mt][nt][i] = 0.0f;

    stage(0, 0);
    cp_commit();

    for (int kt = 0; kt < DMODEL / 32; kt++) {
        if (kt + 1 < DMODEL / 32) {
            stage((kt + 1) & 1, (kt + 1) * 32);
            cp_commit();
            cp_wait<1>();
        } else {
            cp_wait<0>();
        }
        __syncthreads();

        const uint32_t* W  = smw + (kt & 1) * 4 * PLANEW;
        const uint32_t* wAh = W;
        const uint32_t* wAl = W + PLANEW;
        const uint32_t* wBh = W + 2 * PLANEW;
        const uint32_t* wBl = W + 3 * PLANEW;

#pragma unroll
        for (int ks = 0; ks < 2; ks++) {
            const int wb = ks * 8;

            uint32_t ah[2][4], al[2][4];
#pragma unroll
            for (int mt = 0; mt < 2; mt++) {
                const int r0 = wm * 32 + mt * 16 + gID;
                ah[mt][0] = wAh[r0 * SWG + wb + tg];
                ah[mt][1] = wAh[(r0 + 8) * SWG + wb + tg];
                ah[mt][2] = wAh[r0 * SWG + wb + tg + 4];
                ah[mt][3] = wAh[(r0 + 8) * SWG + wb + tg + 4];
                al[mt][0] = wAl[r0 * SWG + wb + tg];
                al[mt][1] = wAl[(r0 + 8) * SWG + wb + tg];
                al[mt][2] = wAl[r0 * SWG + wb + tg + 4];
                al[mt][3] = wAl[(r0 + 8) * SWG + wb + tg + 4];
            }

#pragma unroll
            for (int nt = 0; nt < 8; nt++) {
                const int c0 = wn * 64 + nt * 8 + gID;
                uint32_t bh0 = wBh[c0 * SWG + wb + tg];
                uint32_t bh1 = wBh[c0 * SWG + wb + tg + 4];
                uint32_t bl0 = wBl[c0 * SWG + wb + tg];
                uint32_t bl1 = wBl[c0 * SWG + wb + tg + 4];
#pragma unroll
                for (int mt = 0; mt < 2; mt++) {
                    mma_bf16(acc[mt][nt], ah[mt][0], ah[mt][1], ah[mt][2], ah[mt][3], bh0, bh1);
                    mma_bf16(acc[mt][nt], ah[mt][0], ah[mt][1], ah[mt][2], ah[mt][3], bl0, bl1);
                    mma_bf16(acc[mt][nt], al[mt][0], al[mt][1], al[mt][2], al[mt][3], bh0, bh1);
                }
            }
        }
        __syncthreads();
    }

    if (MODE == 1) {
        const size_t zo = (size_t)blockIdx.z * (BHEADS * SEQ * HDIM);
#pragma unroll
        for (int mt = 0; mt < 2; mt++) {
            const int rbase = brow + wm * 32 + mt * 16 + gID;
#pragma unroll
            for (int nt = 0; nt < 8; nt++) {
                const int col = bcol + wn * 64 + nt * 8 + tg * 2;
                const int h = col >> 6;
                const int e = col & 63;
#pragma unroll
                for (int half = 0; half < 2; half++) {
                    const int r = rbase + half * 8;
                    const int b = r >> 11;
                    const int s = r & (SEQ - 1);
                    const size_t o = zo + ((size_t)(b * NHEADS + h) * SEQ + s) * HDIM + e;
                    __nv_bfloat16 h0, l0, h1, l1;
                    split_bf(acc[mt][nt][half * 2 + 0], h0, l0);
                    split_bf(acc[mt][nt][half * 2 + 1], h1, l1);
                    *(uint32_t*)(g_qkvh + o) = pack2(h0, h1);
                    *(uint32_t*)(g_qkvl + o) = pack2(l0, l1);
                }
            }
        }
    } else {
#pragma unroll
        for (int mt = 0; mt < 2; mt++) {
            const int rbase = brow + wm * 32 + mt * 16 + gID;
#pragma unroll
            for (int nt = 0; nt < 8; nt++) {
                const int col = bcol + wn * 64 + nt * 8 + tg * 2;
#pragma unroll
                for (int half = 0; half < 2; half++) {
                    const int r = rbase + half * 8;
                    float2 v = make_float2(acc[mt][nt][half * 2], acc[mt][nt][half * 2 + 1]);
                    *(float2*)(Cout + (size_t)r * DMODEL + col) = v;
                }
            }
        }
    }
}

// ---------------------------------------------------------------------------
// bf16x3 flash attention (causal). 128 queries/block, 8 warps, 64-key tiles.
// All fragments via ldmatrix.x4 (Q,K non-trans; V trans from row-major tile).
// P stays in registers (C-frag layout == A-frag layout). No P/V-transpose smem.
// ---------------------------------------------------------------------------
#define BQ   128
#define BKT  64
#define SWF  36                      // words per row (32 data + 4 pad)
#define QW   (BQ * SWF)              // 4608
#define KW   (BKT * SWF)             // 2304
#define FSMEM_W (2*QW + 4*KW)        // 18432 words = 73728 B

__global__ __launch_bounds__(256)
void flash_bf()
{
    extern __shared__ uint32_t smw[];

    const int tid  = threadIdx.x;
    const int lane = tid & 31;
    const int wid  = tid >> 5;
    const int gID  = lane >> 2;
    const int tg   = lane & 3;

    const int bh    = blockIdx.y;
    const int b     = bh >> 4;
    const int h     = bh & 15;
    const int qi    = (int)gridDim.x - 1 - (int)blockIdx.x;
    const int qbase = qi * BQ;

    const __nv_bfloat16* Qhp = g_qkvh + (size_t)bh * (SEQ * HDIM);
    const __nv_bfloat16* Qlp = g_qkvl + (size_t)bh * (SEQ * HDIM);
    const __nv_bfloat16* Khp = g_qkvh + (size_t)(BHEADS + bh) * (SEQ * HDIM);
    const __nv_bfloat16* Klp = g_qkvl + (size_t)(BHEADS + bh) * (SEQ * HDIM);
    const __nv_bfloat16* Vhp = g_qkvh + (size_t)(2 * BHEADS + bh) * (SEQ * HDIM);
    const __nv_bfloat16* Vlp = g_qkvl + (size_t)(2 * BHEADS + bh) * (SEQ * HDIM);

    const uint32_t smem0 = (uint32_t)__cvta_generic_to_shared(smw);
    const uint32_t Qh_b = smem0;
    const uint32_t Ql_b = Qh_b + QW * 4u;
    const uint32_t Kh_b = Ql_b + QW * 4u;
    const uint32_t Kl_b = Kh_b + KW * 4u;
    const uint32_t Vh_b = Kl_b + KW * 4u;
    const uint32_t Vl_b = Vh_b + KW * 4u;

    // ---- Q staging (once) ----
    {
        const int r  = tid >> 1;
        const int c0 = (tid & 1) * 4;
        const __nv_bfloat16* sh = Qhp + (size_t)(qbase + r) * HDIM;
        const __nv_bfloat16* sl = Qlp + (size_t)(qbase + r) * HDIM;
#pragma unroll
        for (int j = 0; j < 4; j++) {
            const int c = c0 + j;
            cp16(Qh_b + (uint32_t)(r * SWF + c * 4) * 4u, sh + c * 8);
            cp16(Ql_b + (uint32_t)(r * SWF + c * 4) * 4u, sl + c * 8);
        }
        cp_commit();
    }

    // ldmatrix per-lane row/col selectors
    const int l7  = lane & 7;
    const int l15 = lane & 15;
    const int lb8 = (lane >> 3) & 1;
    const int lb16 = (lane >> 4) & 1;

    const int rloc = wid * 16 + gID;

    float m0 = -1e30f, m1 = -1e30f, l0 = 0.0f, l1 = 0.0f;
    float oacc[8][4];
#pragma unroll
    for (int nt = 0; nt < 8; nt++)
#pragma unroll
        for (int i = 0; i < 4; i++) oacc[nt][i] = 0.0f;

    const int nkt = 2 * qi + 2;
    for (int kt = 0; kt < nkt; kt++) {
        __syncthreads();   // previous tile's K/V reads complete

        // ---- Stage K and V (both row-major, cp.async) ----
        {
            const int r  = tid >> 2;           // 0..63
            const int c0 = (tid & 3) * 2;      // chunks c0, c0+1
            const __nv_bfloat16* skh = Khp + (size_t)(kt * BKT + r) * HDIM;
            const __nv_bfloat16* skl = Klp + (size_t)(kt * BKT + r) * HDIM;
            const __nv_bfloat16* svh = Vhp + (size_t)(kt * BKT + r) * HDIM;
            const __nv_bfloat16* svl = Vlp + (size_t)(kt * BKT + r) * HDIM;
#pragma unroll
            for (int j = 0; j < 2; j++) {
                const int c = c0 + j;
                const uint32_t so = (uint32_t)(r * SWF + c * 4) * 4u;
                cp16(Kh_b + so, skh + c * 8);
                cp16(Kl_b + so, skl + c * 8);
                cp16(Vh_b + so, svh + c * 8);
                cp16(Vl_b + so, svl + c * 8);
            }
            cp_commit();
        }
        cp_wait<0>();
        __syncthreads();

        // ---- S = Q K^T (3x bf16) ----
        float sacc[8][4];
#pragma unroll
        for (int nt = 0; nt < 8; nt++)
#pragma unroll
            for (int i = 0; i < 4; i++) sacc[nt][i] = 0.0f;

#pragma unroll
        for (int ks = 0; ks < 4; ks++) {
            uint32_t qh[4], ql[4];
            const uint32_t qoff = (uint32_t)((rloc - gID + l15) * SWF + 8 * ks + 4 * lb16) * 4u;
            ldsm4(qh, Qh_b + qoff);
            ldsm4(ql, Ql_b + qoff);
#pragma unroll
            for (int np = 0; np < 4; np++) {
                uint32_t kh[4], kl[4];
                const uint32_t koff =
                    (uint32_t)((np * 16 + l7 + lb16 * 8) * SWF + 8 * ks + 4 * lb8) * 4u;
                ldsm4(kh, Kh_b + koff);
                ldsm4(kl, Kl_b + koff);
                mma_bf16(sacc[2 * np],     qh[0], qh[1], qh[2], qh[3], kh[0], kh[1]);
                mma_bf16(sacc[2 * np],     qh[0], qh[1], qh[2], qh[3], kl[0], kl[1]);
                mma_bf16(sacc[2 * np],     ql[0], ql[1], ql[2], ql[3], kh[0], kh[1]);
                mma_bf16(sacc[2 * np + 1], qh[0], qh[1], qh[2], qh[3], kh[2], kh[3]);
                mma_bf16(sacc[2 * np + 1], qh[0], qh[1], qh[2], qh[3], kl[2], kl[3]);
                mma_bf16(sacc[2 * np + 1], ql[0], ql[1], ql[2], ql[3], kh[2], kh[3]);
            }
        }

        // ---- Online softmax; build P A-fragments in registers ----
        const bool diag = (kt >= 2 * qi);
        const float scale = 0.125f;
        uint32_t pfh[4][4], pfl[4][4];

#pragma unroll
        for (int half = 0; half < 2; half++) {
            const int rg = qbase + rloc + half * 8;
            float& m = half ? m1 : m0;
            float& l = half ? l1 : l0;

            float mx = -1e30f;
#pragma unroll
            for (int nt = 0; nt < 8; nt++) {
#pragma unroll
                for (int j = 0; j < 2; j++) {
                    float s = sacc[nt][half * 2 + j] * scale;
                    if (diag) {
                        const int cg = kt * BKT + nt * 8 + tg * 2 + j;
                        if (cg > rg) s = -1e30f;
                    }
                    sacc[nt][half * 2 + j] = s;
                    mx = fmaxf(mx, s);
                }
            }
            mx = fmaxf(mx, __shfl_xor_sync(0xffffffffu, mx, 1));
            mx = fmaxf(mx, __shfl_xor_sync(0xffffffffu, mx, 2));

            const float mn = fmaxf(m, mx);
            const float alpha = __expf(m - mn);
            float rs = 0.0f;
#pragma unroll
            for (int nt = 0; nt < 8; nt++) {
                float p0 = __expf(sacc[nt][half * 2 + 0] - mn);
                float p1 = __expf(sacc[nt][half * 2 + 1] - mn);
                rs += p0 + p1;
                __nv_bfloat16 h0, lo0, h1, lo1;
                split_bf(p0, h0, lo0);
                split_bf(p1, h1, lo1);
                const int ks   = nt >> 1;
                const int slot = (nt & 1) * 2 + half;
                pfh[ks][slot] = pack2(h0, h1);
                pfl[ks][slot] = pack2(lo0, lo1);
            }
            rs += __shfl_xor_sync(0xffffffffu, rs, 1);
            rs += __shfl_xor_sync(0xffffffffu, rs, 2);
            l = l * alpha + rs;
            m = mn;
#pragma unroll
            for (int nt = 0; nt < 8; nt++) {
                oacc[nt][half * 2 + 0] *= alpha;
                oacc[nt][half * 2 + 1] *= alpha;
            }
        }

        // ---- O += P V (V B-frags via ldmatrix.trans from row-major tile) ----
#pragma unroll
        for (int ks = 0; ks < 4; ks++) {
#pragma unroll
            for (int np = 0; np < 4; np++) {
                uint32_t vh[4], vl[4];
                const uint32_t voff =
                    (uint32_t)((ks * 16 + l7 + lb8 * 8) * SWF + 8 * np + 4 * lb16) * 4u;
                ldsm4t(vh, Vh_b + voff);
                ldsm4t(vl, Vl_b + voff);
                mma_bf16(oacc[2 * np],     pfh[ks][0], pfh[ks][1], pfh[ks][2], pfh[ks][3], vh[0], vh[1]);
                mma_bf16(oacc[2 * np],     pfh[ks][0], pfh[ks][1], pfh[ks][2], pfh[ks][3], vl[0], vl[1]);
                mma_bf16(oacc[2 * np],     pfl[ks][0], pfl[ks][1], pfl[ks][2], pfl[ks][3], vh[0], vh[1]);
                mma_bf16(oacc[2 * np + 1], pfh[ks][0], pfh[ks][1], pfh[ks][2], pfh[ks][3], vh[2], vh[3]);
                mma_bf16(oacc[2 * np + 1], pfh[ks][0], pfh[ks][1], pfh[ks][2], pfh[ks][3], vl[2], vl[3]);
                mma_bf16(oacc[2 * np + 1], pfl[ks][0], pfl[ks][1], pfl[ks][2], pfl[ks][3], vh[2], vh[3]);
            }
        }
    }

    // ---- Epilogue: normalize, split, write ctx planes ----
    const float inv0 = 1.0f / l0;
    const float inv1 = 1.0f / l1;
#pragma unroll
    for (int half = 0; half < 2; half++) {
        const float inv = half ? inv1 : inv0;
        const int rg = qbase + rloc + half * 8;
        const size_t rowo = ((size_t)b * SEQ + rg) * DMODEL + h * HDIM;
#pragma unroll
        for (int nt = 0; nt < 8; nt++) {
            float v0 = oacc[nt][half * 2 + 0] * inv;
            float v1 = oacc[nt][half * 2 + 1] * inv;
            __nv_bfloat16 h0, lo0, h1, lo1;
            split_bf(v0, h0, lo0);
            split_bf(v1, h1, lo1);
            const size_t o = rowo + nt * 8 + tg * 2;
            *(uint32_t*)(g_ctxh + o) = pack2(h0, h1);
            *(uint32_t*)(g_ctxl + o) = pack2(lo0, lo1);
        }
    }
}

// ---------------------------------------------------------------------------
extern "C" void kernel_launch(void* const* d_in, const int* in_sizes, int n_in,
                              void* d_out, int out_size)
{
    const float* x  = (const float*)d_in[0];
    const float* Wq = (const float*)d_in[1];
    const float* Wk = (const float*)d_in[2];
    const float* Wv = (const float*)d_in[3];
    const float* Wo = (const float*)d_in[4];
    float* out = (float*)d_out;

    const int gsmem = GSMEM_W * 4;     // 81920 B
    const int fsmem = FSMEM_W * 4;     // 73728 B

    cudaFuncSetAttribute(gemm_bf<1>,
                         cudaFuncAttributeMaxDynamicSharedMemorySize, gsmem);
    cudaFuncSetAttribute(gemm_bf<0>,
                         cudaFuncAttributeMaxDynamicSharedMemorySize, gsmem);
    cudaFuncSetAttribute(flash_bf,
                         cudaFuncAttributeMaxDynamicSharedMemorySize, fsmem);

    __nv_bfloat16 *xh, *xl;
    cudaGetSymbolAddress((void**)&xh, g_xh);
    cudaGetSymbolAddress((void**)&xl, g_xl);

    const int nx = ROWS * DMODEL;
    const int nw = DMODEL * DMODEL;
    split_kernel<<<(nx / 4 + 255) / 256, 256>>>(x, xh, xl, nx);
    dim3 gs((nw / 4 + 255) / 256, 4);
    split4_kernel<<<gs, 256>>>(Wq, Wk, Wv, Wo);

    // 1) QKV projections
    dim3 g1(DMODEL / 128, ROWS / 128, 3);
    gemm_bf<1><<<g1, 256, gsmem>>>(nullptr);

    // 2) Causal flash attention
    dim3 g2(SEQ / BQ, BHEADS);
    flash_bf<<<g2, 256, fsmem>>>();

    // 3) Output projection
    dim3 g3(DMODEL / 128, ROWS / 128, 1);
    gemm_bf<0><<<g3, 256, gsmem>>>(out);
}

// round 9
// speedup vs baseline: 2.6021x; 1.1648x over previous
#include <cuda_runtime.h>
#include <cuda_bf16.h>
#include <cstdint>

#define BATCH   4
#define SEQ     2048
#define DMODEL  1024
#define NHEADS  16
#define HDIM    64
#define BHEADS  (BATCH * NHEADS)        // 64
#define ROWS    (BATCH * SEQ)           // 8192

// ---------------------------------------------------------------------------
// Device-global scratch (bf16 hi/lo planes)
// ---------------------------------------------------------------------------
__device__ __nv_bfloat16 g_xh[(size_t)ROWS * DMODEL];
__device__ __nv_bfloat16 g_xl[(size_t)ROWS * DMODEL];
__device__ __nv_bfloat16 g_wh[4u * DMODEL * DMODEL];   // q,k,v,o  (n x k row-major)
__device__ __nv_bfloat16 g_wl[4u * DMODEL * DMODEL];
__device__ __nv_bfloat16 g_qkvh[3u * BHEADS * SEQ * HDIM];  // [which][bh][s][e]
__device__ __nv_bfloat16 g_qkvl[3u * BHEADS * SEQ * HDIM];
__device__ __nv_bfloat16 g_ctxh[(size_t)ROWS * DMODEL];
__device__ __nv_bfloat16 g_ctxl[(size_t)ROWS * DMODEL];

// ---------------------------------------------------------------------------
// Helpers
// ---------------------------------------------------------------------------
__device__ __forceinline__ void mma_bf16(float* c,
                                         uint32_t a0, uint32_t a1, uint32_t a2, uint32_t a3,
                                         uint32_t b0, uint32_t b1) {
    asm volatile(
        "mma.sync.aligned.m16n8k16.row.col.f32.bf16.bf16.f32 "
        "{%0,%1,%2,%3}, {%4,%5,%6,%7}, {%8,%9}, {%0,%1,%2,%3};\n"
        : "+f"(c[0]), "+f"(c[1]), "+f"(c[2]), "+f"(c[3])
        : "r"(a0), "r"(a1), "r"(a2), "r"(a3), "r"(b0), "r"(b1));
}

__device__ __forceinline__ void ldsm4(uint32_t* r, uint32_t addr) {
    asm volatile("ldmatrix.sync.aligned.m8n8.x4.shared.b16 {%0,%1,%2,%3}, [%4];"
                 : "=r"(r[0]), "=r"(r[1]), "=r"(r[2]), "=r"(r[3]) : "r"(addr));
}
__device__ __forceinline__ void ldsm4t(uint32_t* r, uint32_t addr) {
    asm volatile("ldmatrix.sync.aligned.m8n8.x4.trans.shared.b16 {%0,%1,%2,%3}, [%4];"
                 : "=r"(r[0]), "=r"(r[1]), "=r"(r[2]), "=r"(r[3]) : "r"(addr));
}

__device__ __forceinline__ void cp16(uint32_t smem_dst, const void* gmem_src) {
    asm volatile("cp.async.cg.shared.global [%0], [%1], 16;\n"
                 :: "r"(smem_dst), "l"(gmem_src));
}
__device__ __forceinline__ void cp_commit() {
    asm volatile("cp.async.commit_group;\n");
}
template <int N>
__device__ __forceinline__ void cp_wait() {
    asm volatile("cp.async.wait_group %0;\n" :: "n"(N));
}

__device__ __forceinline__ void split_bf(float x, __nv_bfloat16& h, __nv_bfloat16& l) {
    h = __float2bfloat16(x);
    l = __float2bfloat16(x - __bfloat162float(h));
}
__device__ __forceinline__ uint32_t pack2(__nv_bfloat16 a, __nv_bfloat16 b) {
    return (uint32_t)__bfloat16_as_ushort(a) | ((uint32_t)__bfloat16_as_ushort(b) << 16);
}

// ---------------------------------------------------------------------------
// Pre-split kernels
// ---------------------------------------------------------------------------
__global__ void split_kernel(const float* __restrict__ src,
                             __nv_bfloat16* __restrict__ hi,
                             __nv_bfloat16* __restrict__ lo, int n)
{
    int i = (blockIdx.x * blockDim.x + threadIdx.x) * 4;
    if (i >= n) return;
    float4 v = *(const float4*)(src + i);
    __nv_bfloat16 h0, l0, h1, l1, h2, l2, h3, l3;
    split_bf(v.x, h0, l0); split_bf(v.y, h1, l1);
    split_bf(v.z, h2, l2); split_bf(v.w, h3, l3);
    *(uint32_t*)(hi + i)     = pack2(h0, h1);
    *(uint32_t*)(hi + i + 2) = pack2(h2, h3);
    *(uint32_t*)(lo + i)     = pack2(l0, l1);
    *(uint32_t*)(lo + i + 2) = pack2(l2, l3);
}

__global__ void split4_kernel(const float* __restrict__ W0, const float* __restrict__ W1,
                              const float* __restrict__ W2, const float* __restrict__ W3)
{
    const int z = blockIdx.y;
    const float* src = (z == 0) ? W0 : (z == 1) ? W1 : (z == 2) ? W2 : W3;
    const size_t nw = (size_t)DMODEL * DMODEL;
    __nv_bfloat16* hi = g_wh + z * nw;
    __nv_bfloat16* lo = g_wl + z * nw;
    int i = (blockIdx.x * blockDim.x + threadIdx.x) * 4;
    if (i >= (int)nw) return;
    float4 v = *(const float4*)(src + i);
    __nv_bfloat16 h0, l0, h1, l1, h2, l2, h3, l3;
    split_bf(v.x, h0, l0); split_bf(v.y, h1, l1);
    split_bf(v.z, h2, l2); split_bf(v.w, h3, l3);
    *(uint32_t*)(hi + i)     = pack2(h0, h1);
    *(uint32_t*)(hi + i + 2) = pack2(h2, h3);
    *(uint32_t*)(lo + i)     = pack2(l0, l1);
    *(uint32_t*)(lo + i + 2) = pack2(l2, l3);
}

// ---------------------------------------------------------------------------
// bf16x3 GEMM with ldmatrix fragments: C = A (MxK rm) * B^T (B NxK rm).
// 128x128 block, BK=32, 8 warps (4 wm x 2 wn), warp tile 32x64.
// ---------------------------------------------------------------------------
#define SWG     20
#define PLANEW  (128 * SWG)
#define GSMEM_W (2 * 4 * PLANEW)

template <int MODE>
__global__ __launch_bounds__(256, 2)
void gemm_bf(float* __restrict__ Cout)
{
    extern __shared__ uint32_t smw[];

    const __nv_bfloat16 *Ah, *Al, *Bh, *Bl;
    if (MODE == 1) {
        Ah = g_xh;  Al = g_xl;
        const size_t wo = (size_t)blockIdx.z * DMODEL * DMODEL;
        Bh = g_wh + wo;  Bl = g_wl + wo;
    } else {
        Ah = g_ctxh;  Al = g_ctxl;
        Bh = g_wh + 3u * DMODEL * DMODEL;  Bl = g_wl + 3u * DMODEL * DMODEL;
    }

    const int tid  = threadIdx.x;
    const int lane = tid & 31;
    const int wid  = tid >> 5;
    const int wm   = wid >> 1;
    const int wn   = wid & 1;
    const int gID  = lane >> 2;
    const int tg   = lane & 3;

    // ldmatrix lane selectors
    const int l7   = lane & 7;
    const int l15  = lane & 15;
    const int lb8  = (lane >> 3) & 1;
    const int lb16 = (lane >> 4) & 1;

    const int brow = blockIdx.y * 128;
    const int bcol = blockIdx.x * 128;

    const int srow = tid >> 1;
    const int cb   = (tid & 1) * 2;

    const uint32_t smem0 = (uint32_t)__cvta_generic_to_shared(smw);

    auto stage = [&](int buf, int k0) {
        const uint32_t base = smem0 + (uint32_t)(buf * 4 * PLANEW) * 4u;
        const __nv_bfloat16* gsrc[4] = {
            Ah + (size_t)(brow + srow) * DMODEL + k0,
            Al + (size_t)(brow + srow) * DMODEL + k0,
            Bh + (size_t)(bcol + srow) * DMODEL + k0,
            Bl + (size_t)(bcol + srow) * DMODEL + k0 };
#pragma unroll
        for (int p = 0; p < 4; p++) {
#pragma unroll
            for (int j = 0; j < 2; j++) {
                const int c = cb + j;
                cp16(base + (uint32_t)(p * PLANEW + srow * SWG + c * 4) * 4u,
                     gsrc[p] + c * 8);
            }
        }
    };

    float acc[2][8][4];
#pragma unroll
    for (int mt = 0; mt < 2; mt++)
#pragma unroll
        for (int nt = 0; nt < 8; nt++)
#pragma unroll
            for (int i = 0; i < 4; i++) acc[mt][nt][i] = 0.0f;

    stage(0, 0);
    cp_commit();

    for (int kt = 0; kt < DMODEL / 32; kt++) {
        if (kt + 1 < DMODEL / 32) {
            stage((kt + 1) & 1, (kt + 1) * 32);
            cp_commit();
            cp_wait<1>();
        } else {
            cp_wait<0>();
        }
        __syncthreads();

        const uint32_t bufw = (uint32_t)((kt & 1) * 4 * PLANEW) * 4u;
        const uint32_t Ah_b = smem0 + bufw;
        const uint32_t Al_b = Ah_b + PLANEW * 4u;
        const uint32_t Bh_b = Al_b + PLANEW * 4u;
        const uint32_t Bl_b = Bh_b + PLANEW * 4u;

#pragma unroll
        for (int ks = 0; ks < 2; ks++) {
            const int wb = ks * 8;

            // A fragments: 2 m16 tiles, ldmatrix.x4 each (Q-pattern)
            uint32_t ah[2][4], al[2][4];
#pragma unroll
            for (int mt = 0; mt < 2; mt++) {
                const uint32_t aoff =
                    (uint32_t)((wm * 32 + mt * 16 + l15) * SWG + wb + 4 * lb16) * 4u;
                ldsm4(ah[mt], Ah_b + aoff);
                ldsm4(al[mt], Al_b + aoff);
            }

            // B fragments: 4 n16 groups (2 n8 tiles each), ldmatrix.x4 (K-pattern)
#pragma unroll
            for (int np = 0; np < 4; np++) {
                uint32_t bhf[4], blf[4];
                const uint32_t boff =
                    (uint32_t)((wn * 64 + np * 16 + l7 + lb16 * 8) * SWG + wb + 4 * lb8) * 4u;
                ldsm4(bhf, Bh_b + boff);
                ldsm4(blf, Bl_b + boff);
#pragma unroll
                for (int half = 0; half < 2; half++) {
                    const int nt = 2 * np + half;
                    const uint32_t bh0 = bhf[2 * half], bh1 = bhf[2 * half + 1];
                    const uint32_t bl0 = blf[2 * half], bl1 = blf[2 * half + 1];
#pragma unroll
                    for (int mt = 0; mt < 2; mt++) {
                        mma_bf16(acc[mt][nt], ah[mt][0], ah[mt][1], ah[mt][2], ah[mt][3], bh0, bh1);
                        mma_bf16(acc[mt][nt], ah[mt][0], ah[mt][1], ah[mt][2], ah[mt][3], bl0, bl1);
                        mma_bf16(acc[mt][nt], al[mt][0], al[mt][1], al[mt][2], al[mt][3], bh0, bh1);
                    }
                }
            }
        }
        __syncthreads();
    }

    if (MODE == 1) {
        const size_t zo = (size_t)blockIdx.z * (BHEADS * SEQ * HDIM);
#pragma unroll
        for (int mt = 0; mt < 2; mt++) {
            const int rbase = brow + wm * 32 + mt * 16 + gID;
#pragma unroll
            for (int nt = 0; nt < 8; nt++) {
                const int col = bcol + wn * 64 + nt * 8 + tg * 2;
                const int h = col >> 6;
                const int e = col & 63;
#pragma unroll
                for (int half = 0; half < 2; half++) {
                    const int r = rbase + half * 8;
                    const int b = r >> 11;
                    const int s = r & (SEQ - 1);
                    const size_t o = zo + ((size_t)(b * NHEADS + h) * SEQ + s) * HDIM + e;
                    __nv_bfloat16 h0, l0, h1, l1;
                    split_bf(acc[mt][nt][half * 2 + 0], h0, l0);
                    split_bf(acc[mt][nt][half * 2 + 1], h1, l1);
                    *(uint32_t*)(g_qkvh + o) = pack2(h0, h1);
                    *(uint32_t*)(g_qkvl + o) = pack2(l0, l1);
                }
            }
        }
    } else {
#pragma unroll
        for (int mt = 0; mt < 2; mt++) {
            const int rbase = brow + wm * 32 + mt * 16 + gID;
#pragma unroll
            for (int nt = 0; nt < 8; nt++) {
                const int col = bcol + wn * 64 + nt * 8 + tg * 2;
#pragma unroll
                for (int half = 0; half < 2; half++) {
                    const int r = rbase + half * 8;
                    float2 v = make_float2(acc[mt][nt][half * 2], acc[mt][nt][half * 2 + 1]);
                    *(float2*)(Cout + (size_t)r * DMODEL + col) = v;
                }
            }
        }
    }
}

// ---------------------------------------------------------------------------
// bf16x3 flash attention (causal) — R8 structure + 2 CTAs/SM.
// ---------------------------------------------------------------------------
#define BQ   128
#define BKT  64
#define SWF  36
#define QW   (BQ * SWF)
#define KW   (BKT * SWF)
#define FSMEM_W (2*QW + 4*KW)        // 73728 B

__global__ __launch_bounds__(256, 2)
void flash_bf()
{
    extern __shared__ uint32_t smw[];

    const int tid  = threadIdx.x;
    const int lane = tid & 31;
    const int wid  = tid >> 5;
    const int gID  = lane >> 2;
    const int tg   = lane & 3;

    const int bh    = blockIdx.y;
    const int b     = bh >> 4;
    const int h     = bh & 15;
    const int qi    = (int)gridDim.x - 1 - (int)blockIdx.x;
    const int qbase = qi * BQ;

    const __nv_bfloat16* Qhp = g_qkvh + (size_t)bh * (SEQ * HDIM);
    const __nv_bfloat16* Qlp = g_qkvl + (size_t)bh * (SEQ * HDIM);
    const __nv_bfloat16* Khp = g_qkvh + (size_t)(BHEADS + bh) * (SEQ * HDIM);
    const __nv_bfloat16* Klp = g_qkvl + (size_t)(BHEADS + bh) * (SEQ * HDIM);
    const __nv_bfloat16* Vhp = g_qkvh + (size_t)(2 * BHEADS + bh) * (SEQ * HDIM);
    const __nv_bfloat16* Vlp = g_qkvl + (size_t)(2 * BHEADS + bh) * (SEQ * HDIM);

    const uint32_t smem0 = (uint32_t)__cvta_generic_to_shared(smw);
    const uint32_t Qh_b = smem0;
    const uint32_t Ql_b = Qh_b + QW * 4u;
    const uint32_t Kh_b = Ql_b + QW * 4u;
    const uint32_t Kl_b = Kh_b + KW * 4u;
    const uint32_t Vh_b = Kl_b + KW * 4u;
    const uint32_t Vl_b = Vh_b + KW * 4u;

    // ---- Q staging (once) ----
    {
        const int r  = tid >> 1;
        const int c0 = (tid & 1) * 4;
        const __nv_bfloat16* sh = Qhp + (size_t)(qbase + r) * HDIM;
        const __nv_bfloat16* sl = Qlp + (size_t)(qbase + r) * HDIM;
#pragma unroll
        for (int j = 0; j < 4; j++) {
            const int c = c0 + j;
            cp16(Qh_b + (uint32_t)(r * SWF + c * 4) * 4u, sh + c * 8);
            cp16(Ql_b + (uint32_t)(r * SWF + c * 4) * 4u, sl + c * 8);
        }
        cp_commit();
    }

    const int l7  = lane & 7;
    const int l15 = lane & 15;
    const int lb8 = (lane >> 3) & 1;
    const int lb16 = (lane >> 4) & 1;

    const int rloc = wid * 16 + gID;

    float m0 = -1e30f, m1 = -1e30f, l0 = 0.0f, l1 = 0.0f;
    float oacc[8][4];
#pragma unroll
    for (int nt = 0; nt < 8; nt++)
#pragma unroll
        for (int i = 0; i < 4; i++) oacc[nt][i] = 0.0f;

    const int nkt = 2 * qi + 2;
    for (int kt = 0; kt < nkt; kt++) {
        __syncthreads();

        // ---- Stage K and V (row-major, cp.async) ----
        {
            const int r  = tid >> 2;
            const int c0 = (tid & 3) * 2;
            const __nv_bfloat16* skh = Khp + (size_t)(kt * BKT + r) * HDIM;
            const __nv_bfloat16* skl = Klp + (size_t)(kt * BKT + r) * HDIM;
            const __nv_bfloat16* svh = Vhp + (size_t)(kt * BKT + r) * HDIM;
            const __nv_bfloat16* svl = Vlp + (size_t)(kt * BKT + r) * HDIM;
#pragma unroll
            for (int j = 0; j < 2; j++) {
                const int c = c0 + j;
                const uint32_t so = (uint32_t)(r * SWF + c * 4) * 4u;
                cp16(Kh_b + so, skh + c * 8);
                cp16(Kl_b + so, skl + c * 8);
                cp16(Vh_b + so, svh + c * 8);
                cp16(Vl_b + so, svl + c * 8);
            }
            cp_commit();
        }
        cp_wait<0>();
        __syncthreads();

        // ---- S = Q K^T ----
        float sacc[8][4];
#pragma unroll
        for (int nt = 0; nt < 8; nt++)
#pragma unroll
            for (int i = 0; i < 4; i++) sacc[nt][i] = 0.0f;

#pragma unroll
        for (int ks = 0; ks < 4; ks++) {
            uint32_t qh[4], ql[4];
            const uint32_t qoff = (uint32_t)((rloc - gID + l15) * SWF + 8 * ks + 4 * lb16) * 4u;
            ldsm4(qh, Qh_b + qoff);
            ldsm4(ql, Ql_b + qoff);
#pragma unroll
            for (int np = 0; np < 4; np++) {
                uint32_t kh[4], kl[4];
                const uint32_t koff =
                    (uint32_t)((np * 16 + l7 + lb16 * 8) * SWF + 8 * ks + 4 * lb8) * 4u;
                ldsm4(kh, Kh_b + koff);
                ldsm4(kl, Kl_b + koff);
                mma_bf16(sacc[2 * np],     qh[0], qh[1], qh[2], qh[3], kh[0], kh[1]);
                mma_bf16(sacc[2 * np],     qh[0], qh[1], qh[2], qh[3], kl[0], kl[1]);
                mma_bf16(sacc[2 * np],     ql[0], ql[1], ql[2], ql[3], kh[0], kh[1]);
                mma_bf16(sacc[2 * np + 1], qh[0], qh[1], qh[2], qh[3], kh[2], kh[3]);
                mma_bf16(sacc[2 * np + 1], qh[0], qh[1], qh[2], qh[3], kl[2], kl[3]);
                mma_bf16(sacc[2 * np + 1], ql[0], ql[1], ql[2], ql[3], kh[2], kh[3]);
            }
        }

        // ---- Online softmax; P A-fragments in registers ----
        const bool diag = (kt >= 2 * qi);
        const float scale = 0.125f;
        uint32_t pfh[4][4], pfl[4][4];

#pragma unroll
        for (int half = 0; half < 2; half++) {
            const int rg = qbase + rloc + half * 8;
            float& m = half ? m1 : m0;
            float& l = half ? l1 : l0;

            float mx = -1e30f;
#pragma unroll
            for (int nt = 0; nt < 8; nt++) {
#pragma unroll
                for (int j = 0; j < 2; j++) {
                    float s = sacc[nt][half * 2 + j] * scale;
                    if (diag) {
                        const int cg = kt * BKT + nt * 8 + tg * 2 + j;
                        if (cg > rg) s = -1e30f;
                    }
                    sacc[nt][half * 2 + j] = s;
                    mx = fmaxf(mx, s);
                }
            }
            mx = fmaxf(mx, __shfl_xor_sync(0xffffffffu, mx, 1));
            mx = fmaxf(mx, __shfl_xor_sync(0xffffffffu, mx, 2));

            const float mn = fmaxf(m, mx);
            const float alpha = __expf(m - mn);
            float rs = 0.0f;
#pragma unroll
            for (int nt = 0; nt < 8; nt++) {
                float p0 = __expf(sacc[nt][half * 2 + 0] - mn);
                float p1 = __expf(sacc[nt][half * 2 + 1] - mn);
                rs += p0 + p1;
                __nv_bfloat16 h0, lo0, h1, lo1;
                split_bf(p0, h0, lo0);
                split_bf(p1, h1, lo1);
                const int ks   = nt >> 1;
                const int slot = (nt & 1) * 2 + half;
                pfh[ks][slot] = pack2(h0, h1);
                pfl[ks][slot] = pack2(lo0, lo1);
            }
            rs += __shfl_xor_sync(0xffffffffu, rs, 1);
            rs += __shfl_xor_sync(0xffffffffu, rs, 2);
            l = l * alpha + rs;
            m = mn;
#pragma unroll
            for (int nt = 0; nt < 8; nt++) {
                oacc[nt][half * 2 + 0] *= alpha;
                oacc[nt][half * 2 + 1] *= alpha;
            }
        }

        // ---- O += P V ----
#pragma unroll
        for (int ks = 0; ks < 4; ks++) {
#pragma unroll
            for (int np = 0; np < 4; np++) {
                uint32_t vh[4], vl[4];
                const uint32_t voff =
                    (uint32_t)((ks * 16 + l7 + lb8 * 8) * SWF + 8 * np + 4 * lb16) * 4u;
                ldsm4t(vh, Vh_b + voff);
                ldsm4t(vl, Vl_b + voff);
                mma_bf16(oacc[2 * np],     pfh[ks][0], pfh[ks][1], pfh[ks][2], pfh[ks][3], vh[0], vh[1]);
                mma_bf16(oacc[2 * np],     pfh[ks][0], pfh[ks][1], pfh[ks][2], pfh[ks][3], vl[0], vl[1]);
                mma_bf16(oacc[2 * np],     pfl[ks][0], pfl[ks][1], pfl[ks][2], pfl[ks][3], vh[0], vh[1]);
                mma_bf16(oacc[2 * np + 1], pfh[ks][0], pfh[ks][1], pfh[ks][2], pfh[ks][3], vh[2], vh[3]);
                mma_bf16(oacc[2 * np + 1], pfh[ks][0], pfh[ks][1], pfh[ks][2], pfh[ks][3], vl[2], vl[3]);
                mma_bf16(oacc[2 * np + 1], pfl[ks][0], pfl[ks][1], pfl[ks][2], pfl[ks][3], vh[2], vh[3]);
            }
        }
    }

    // ---- Epilogue ----
    const float inv0 = 1.0f / l0;
    const float inv1 = 1.0f / l1;
#pragma unroll
    for (int half = 0; half < 2; half++) {
        const float inv = half ? inv1 : inv0;
        const int rg = qbase + rloc + half * 8;
        const size_t rowo = ((size_t)b * SEQ + rg) * DMODEL + h * HDIM;
#pragma unroll
        for (int nt = 0; nt < 8; nt++) {
            float v0 = oacc[nt][half * 2 + 0] * inv;
            float v1 = oacc[nt][half * 2 + 1] * inv;
            __nv_bfloat16 h0, lo0, h1, lo1;
            split_bf(v0, h0, lo0);
            split_bf(v1, h1, lo1);
            const size_t o = rowo + nt * 8 + tg * 2;
            *(uint32_t*)(g_ctxh + o) = pack2(h0, h1);
            *(uint32_t*)(g_ctxl + o) = pack2(lo0, lo1);
        }
    }
}

// ---------------------------------------------------------------------------
extern "C" void kernel_launch(void* const* d_in, const int* in_sizes, int n_in,
                              void* d_out, int out_size)
{
    const float* x  = (const float*)d_in[0];
    const float* Wq = (const float*)d_in[1];
    const float* Wk = (const float*)d_in[2];
    const float* Wv = (const float*)d_in[3];
    const float* Wo = (const float*)d_in[4];
    float* out = (float*)d_out;

    const int gsmem = GSMEM_W * 4;     // 81920 B
    const int fsmem = FSMEM_W * 4;     // 73728 B

    cudaFuncSetAttribute(gemm_bf<1>,
                         cudaFuncAttributeMaxDynamicSharedMemorySize, gsmem);
    cudaFuncSetAttribute(gemm_bf<0>,
                         cudaFuncAttributeMaxDynamicSharedMemorySize, gsmem);
    cudaFuncSetAttribute(flash_bf,
                         cudaFuncAttributeMaxDynamicSharedMemorySize, fsmem);

    __nv_bfloat16 *xh, *xl;
    cudaGetSymbolAddress((void**)&xh, g_xh);
    cudaGetSymbolAddress((void**)&xl, g_xl);

    const int nx = ROWS * DMODEL;
    const int nw = DMODEL * DMODEL;
    split_kernel<<<(nx / 4 + 255) / 256, 256>>>(x, xh, xl, nx);
    dim3 gs((nw / 4 + 255) / 256, 4);
    split4_kernel<<<gs, 256>>>(Wq, Wk, Wv, Wo);

    // 1) QKV projections
    dim3 g1(DMODEL / 128, ROWS / 128, 3);
    gemm_bf<1><<<g1, 256, gsmem>>>(nullptr);

    // 2) Causal flash attention
    dim3 g2(SEQ / BQ, BHEADS);
    flash_bf<<<g2, 256, fsmem>>>();

    // 3) Output projection
    dim3 g3(DMODEL / 128, ROWS / 128, 1);
    gemm_bf<0><<<g3, 256, gsmem>>>(out);
}

// round 10
// speedup vs baseline: 2.6051x; 1.0012x over previous
#include <cuda_runtime.h>
#include <cuda_bf16.h>
#include <cstdint>

#define BATCH   4
#define SEQ     2048
#define DMODEL  1024
#define NHEADS  16
#define HDIM    64
#define BHEADS  (BATCH * NHEADS)        // 64
#define ROWS    (BATCH * SEQ)           // 8192

// ---------------------------------------------------------------------------
// Device-global scratch (bf16 hi/lo planes)
// ---------------------------------------------------------------------------
__device__ __nv_bfloat16 g_xh[(size_t)ROWS * DMODEL];
__device__ __nv_bfloat16 g_xl[(size_t)ROWS * DMODEL];
__device__ __nv_bfloat16 g_wh[4u * DMODEL * DMODEL];   // q,k,v,o  (n x k row-major)
__device__ __nv_bfloat16 g_wl[4u * DMODEL * DMODEL];
__device__ __nv_bfloat16 g_qkvh[3u * BHEADS * SEQ * HDIM];  // [which][bh][s][e]
__device__ __nv_bfloat16 g_qkvl[3u * BHEADS * SEQ * HDIM];
__device__ __nv_bfloat16 g_ctxh[(size_t)ROWS * DMODEL];
__device__ __nv_bfloat16 g_ctxl[(size_t)ROWS * DMODEL];

// ---------------------------------------------------------------------------
// Helpers
// ---------------------------------------------------------------------------
__device__ __forceinline__ void mma_bf16(float* c,
                                         uint32_t a0, uint32_t a1, uint32_t a2, uint32_t a3,
                                         uint32_t b0, uint32_t b1) {
    asm volatile(
        "mma.sync.aligned.m16n8k16.row.col.f32.bf16.bf16.f32 "
        "{%0,%1,%2,%3}, {%4,%5,%6,%7}, {%8,%9}, {%0,%1,%2,%3};\n"
        : "+f"(c[0]), "+f"(c[1]), "+f"(c[2]), "+f"(c[3])
        : "r"(a0), "r"(a1), "r"(a2), "r"(a3), "r"(b0), "r"(b1));
}

__device__ __forceinline__ void ldsm4(uint32_t* r, uint32_t addr) {
    asm volatile("ldmatrix.sync.aligned.m8n8.x4.shared.b16 {%0,%1,%2,%3}, [%4];"
                 : "=r"(r[0]), "=r"(r[1]), "=r"(r[2]), "=r"(r[3]) : "r"(addr));
}
__device__ __forceinline__ void ldsm4t(uint32_t* r, uint32_t addr) {
    asm volatile("ldmatrix.sync.aligned.m8n8.x4.trans.shared.b16 {%0,%1,%2,%3}, [%4];"
                 : "=r"(r[0]), "=r"(r[1]), "=r"(r[2]), "=r"(r[3]) : "r"(addr));
}

__device__ __forceinline__ void cp16(uint32_t smem_dst, const void* gmem_src) {
    asm volatile("cp.async.cg.shared.global [%0], [%1], 16;\n"
                 :: "r"(smem_dst), "l"(gmem_src));
}
__device__ __forceinline__ void cp_commit() {
    asm volatile("cp.async.commit_group;\n");
}
template <int N>
__device__ __forceinline__ void cp_wait() {
    asm volatile("cp.async.wait_group %0;\n" :: "n"(N));
}

__device__ __forceinline__ void split_bf(float x, __nv_bfloat16& h, __nv_bfloat16& l) {
    h = __float2bfloat16(x);
    l = __float2bfloat16(x - __bfloat162float(h));
}
__device__ __forceinline__ uint32_t pack2(__nv_bfloat16 a, __nv_bfloat16 b) {
    return (uint32_t)__bfloat16_as_ushort(a) | ((uint32_t)__bfloat16_as_ushort(b) << 16);
}

// ---------------------------------------------------------------------------
// Pre-split kernels
// ---------------------------------------------------------------------------
__global__ void split_kernel(const float* __restrict__ src,
                             __nv_bfloat16* __restrict__ hi,
                             __nv_bfloat16* __restrict__ lo, int n)
{
    int i = (blockIdx.x * blockDim.x + threadIdx.x) * 4;
    if (i >= n) return;
    float4 v = *(const float4*)(src + i);
    __nv_bfloat16 h0, l0, h1, l1, h2, l2, h3, l3;
    split_bf(v.x, h0, l0); split_bf(v.y, h1, l1);
    split_bf(v.z, h2, l2); split_bf(v.w, h3, l3);
    *(uint32_t*)(hi + i)     = pack2(h0, h1);
    *(uint32_t*)(hi + i + 2) = pack2(h2, h3);
    *(uint32_t*)(lo + i)     = pack2(l0, l1);
    *(uint32_t*)(lo + i + 2) = pack2(l2, l3);
}

__global__ void split4_kernel(const float* __restrict__ W0, const float* __restrict__ W1,
                              const float* __restrict__ W2, const float* __restrict__ W3)
{
    const int z = blockIdx.y;
    const float* src = (z == 0) ? W0 : (z == 1) ? W1 : (z == 2) ? W2 : W3;
    const size_t nw = (size_t)DMODEL * DMODEL;
    __nv_bfloat16* hi = g_wh + z * nw;
    __nv_bfloat16* lo = g_wl + z * nw;
    int i = (blockIdx.x * blockDim.x + threadIdx.x) * 4;
    if (i >= (int)nw) return;
    float4 v = *(const float4*)(src + i);
    __nv_bfloat16 h0, l0, h1, l1, h2, l2, h3, l3;
    split_bf(v.x, h0, l0); split_bf(v.y, h1, l1);
    split_bf(v.z, h2, l2); split_bf(v.w, h3, l3);
    *(uint32_t*)(hi + i)     = pack2(h0, h1);
    *(uint32_t*)(hi + i + 2) = pack2(h2, h3);
    *(uint32_t*)(lo + i)     = pack2(l0, l1);
    *(uint32_t*)(lo + i + 2) = pack2(l2, l3);
}

// ---------------------------------------------------------------------------
// bf16x3 GEMM with ldmatrix fragments (R9, proven).
// ---------------------------------------------------------------------------
#define SWG     20
#define PLANEW  (128 * SWG)
#define GSMEM_W (2 * 4 * PLANEW)

template <int MODE>
__global__ __launch_bounds__(256, 2)
void gemm_bf(float* __restrict__ Cout)
{
    extern __shared__ uint32_t smw[];

    const __nv_bfloat16 *Ah, *Al, *Bh, *Bl;
    if (MODE == 1) {
        Ah = g_xh;  Al = g_xl;
        const size_t wo = (size_t)blockIdx.z * DMODEL * DMODEL;
        Bh = g_wh + wo;  Bl = g_wl + wo;
    } else {
        Ah = g_ctxh;  Al = g_ctxl;
        Bh = g_wh + 3u * DMODEL * DMODEL;  Bl = g_wl + 3u * DMODEL * DMODEL;
    }

    const int tid  = threadIdx.x;
    const int lane = tid & 31;
    const int wid  = tid >> 5;
    const int wm   = wid >> 1;
    const int wn   = wid & 1;
    const int gID  = lane >> 2;
    const int tg   = lane & 3;

    const int l7   = lane & 7;
    const int l15  = lane & 15;
    const int lb8  = (lane >> 3) & 1;
    const int lb16 = (lane >> 4) & 1;

    const int brow = blockIdx.y * 128;
    const int bcol = blockIdx.x * 128;

    const int srow = tid >> 1;
    const int cb   = (tid & 1) * 2;

    const uint32_t smem0 = (uint32_t)__cvta_generic_to_shared(smw);

    auto stage = [&](int buf, int k0) {
        const uint32_t base = smem0 + (uint32_t)(buf * 4 * PLANEW) * 4u;
        const __nv_bfloat16* gsrc[4] = {
            Ah + (size_t)(brow + srow) * DMODEL + k0,
            Al + (size_t)(brow + srow) * DMODEL + k0,
            Bh + (size_t)(bcol + srow) * DMODEL + k0,
            Bl + (size_t)(bcol + srow) * DMODEL + k0 };
#pragma unroll
        for (int p = 0; p < 4; p++) {
#pragma unroll
            for (int j = 0; j < 2; j++) {
                const int c = cb + j;
                cp16(base + (uint32_t)(p * PLANEW + srow * SWG + c * 4) * 4u,
                     gsrc[p] + c * 8);
            }
        }
    };

    float acc[2][8][4];
#pragma unroll
    for (int mt = 0; mt < 2; mt++)
#pragma unroll
        for (int nt = 0; nt < 8; nt++)
#pragma unroll
            for (int i = 0; i < 4; i++) acc[mt][nt][i] = 0.0f;

    stage(0, 0);
    cp_commit();

    for (int kt = 0; kt < DMODEL / 32; kt++) {
        if (kt + 1 < DMODEL / 32) {
            stage((kt + 1) & 1, (kt + 1) * 32);
            cp_commit();
            cp_wait<1>();
        } else {
            cp_wait<0>();
        }
        __syncthreads();

        const uint32_t bufw = (uint32_t)((kt & 1) * 4 * PLANEW) * 4u;
        const uint32_t Ah_b = smem0 + bufw;
        const uint32_t Al_b = Ah_b + PLANEW * 4u;
        const uint32_t Bh_b = Al_b + PLANEW * 4u;
        const uint32_t Bl_b = Bh_b + PLANEW * 4u;

#pragma unroll
        for (int ks = 0; ks < 2; ks++) {
            const int wb = ks * 8;

            uint32_t ah[2][4], al[2][4];
#pragma unroll
            for (int mt = 0; mt < 2; mt++) {
                const uint32_t aoff =
                    (uint32_t)((wm * 32 + mt * 16 + l15) * SWG + wb + 4 * lb16) * 4u;
                ldsm4(ah[mt], Ah_b + aoff);
                ldsm4(al[mt], Al_b + aoff);
            }

#pragma unroll
            for (int np = 0; np < 4; np++) {
                uint32_t bhf[4], blf[4];
                const uint32_t boff =
                    (uint32_t)((wn * 64 + np * 16 + l7 + lb16 * 8) * SWG + wb + 4 * lb8) * 4u;
                ldsm4(bhf, Bh_b + boff);
                ldsm4(blf, Bl_b + boff);
#pragma unroll
                for (int half = 0; half < 2; half++) {
                    const int nt = 2 * np + half;
                    const uint32_t bh0 = bhf[2 * half], bh1 = bhf[2 * half + 1];
                    const uint32_t bl0 = blf[2 * half], bl1 = blf[2 * half + 1];
#pragma unroll
                    for (int mt = 0; mt < 2; mt++) {
                        mma_bf16(acc[mt][nt], ah[mt][0], ah[mt][1], ah[mt][2], ah[mt][3], bh0, bh1);
                        mma_bf16(acc[mt][nt], ah[mt][0], ah[mt][1], ah[mt][2], ah[mt][3], bl0, bl1);
                        mma_bf16(acc[mt][nt], al[mt][0], al[mt][1], al[mt][2], al[mt][3], bh0, bh1);
                    }
                }
            }
        }
        __syncthreads();
    }

    if (MODE == 1) {
        const size_t zo = (size_t)blockIdx.z * (BHEADS * SEQ * HDIM);
#pragma unroll
        for (int mt = 0; mt < 2; mt++) {
            const int rbase = brow + wm * 32 + mt * 16 + gID;
#pragma unroll
            for (int nt = 0; nt < 8; nt++) {
                const int col = bcol + wn * 64 + nt * 8 + tg * 2;
                const int h = col >> 6;
                const int e = col & 63;
#pragma unroll
                for (int half = 0; half < 2; half++) {
                    const int r = rbase + half * 8;
                    const int b = r >> 11;
                    const int s = r & (SEQ - 1);
                    const size_t o = zo + ((size_t)(b * NHEADS + h) * SEQ + s) * HDIM + e;
                    __nv_bfloat16 h0, l0, h1, l1;
                    split_bf(acc[mt][nt][half * 2 + 0], h0, l0);
                    split_bf(acc[mt][nt][half * 2 + 1], h1, l1);
                    *(uint32_t*)(g_qkvh + o) = pack2(h0, h1);
                    *(uint32_t*)(g_qkvl + o) = pack2(l0, l1);
                }
            }
        }
    } else {
#pragma unroll
        for (int mt = 0; mt < 2; mt++) {
            const int rbase = brow + wm * 32 + mt * 16 + gID;
#pragma unroll
            for (int nt = 0; nt < 8; nt++) {
                const int col = bcol + wn * 64 + nt * 8 + tg * 2;
#pragma unroll
                for (int half = 0; half < 2; half++) {
                    const int r = rbase + half * 8;
                    float2 v = make_float2(acc[mt][nt][half * 2], acc[mt][nt][half * 2 + 1]);
                    *(float2*)(Cout + (size_t)r * DMODEL + col) = v;
                }
            }
        }
    }
}

// ---------------------------------------------------------------------------
// bf16x3 flash attention (causal) — R9 + double-buffered K/V staging.
// smem: Q(hi,lo) + 2 x KV buffers (Kh,Kl,Vh,Vl). 110592 B, 2 CTAs/SM.
// ---------------------------------------------------------------------------
#define BQ   128
#define BKT  64
#define SWF  36
#define QW   (BQ * SWF)              // 4608 words
#define KW   (BKT * SWF)             // 2304 words
#define KVBUF_B (4u * KW * 4u)       // one KV buffer: 4 planes
#define FSMEM_W (2*QW + 8*KW)        // 27648 words = 110592 B

__global__ __launch_bounds__(256, 2)
void flash_bf()
{
    extern __shared__ uint32_t smw[];

    const int tid  = threadIdx.x;
    const int lane = tid & 31;
    const int wid  = tid >> 5;
    const int gID  = lane >> 2;
    const int tg   = lane & 3;

    const int bh    = blockIdx.y;
    const int b     = bh >> 4;
    const int h     = bh & 15;
    const int qi    = (int)gridDim.x - 1 - (int)blockIdx.x;
    const int qbase = qi * BQ;

    const __nv_bfloat16* Qhp = g_qkvh + (size_t)bh * (SEQ * HDIM);
    const __nv_bfloat16* Qlp = g_qkvl + (size_t)bh * (SEQ * HDIM);
    const __nv_bfloat16* Khp = g_qkvh + (size_t)(BHEADS + bh) * (SEQ * HDIM);
    const __nv_bfloat16* Klp = g_qkvl + (size_t)(BHEADS + bh) * (SEQ * HDIM);
    const __nv_bfloat16* Vhp = g_qkvh + (size_t)(2 * BHEADS + bh) * (SEQ * HDIM);
    const __nv_bfloat16* Vlp = g_qkvl + (size_t)(2 * BHEADS + bh) * (SEQ * HDIM);

    const uint32_t smem0 = (uint32_t)__cvta_generic_to_shared(smw);
    const uint32_t Qh_b = smem0;
    const uint32_t Ql_b = Qh_b + QW * 4u;
    const uint32_t KV0  = Ql_b + QW * 4u;

    // ---- Q staging (once) ----
    {
        const int r  = tid >> 1;
        const int c0 = (tid & 1) * 4;
        const __nv_bfloat16* sh = Qhp + (size_t)(qbase + r) * HDIM;
        const __nv_bfloat16* sl = Qlp + (size_t)(qbase + r) * HDIM;
#pragma unroll
        for (int j = 0; j < 4; j++) {
            const int c = c0 + j;
            cp16(Qh_b + (uint32_t)(r * SWF + c * 4) * 4u, sh + c * 8);
            cp16(Ql_b + (uint32_t)(r * SWF + c * 4) * 4u, sl + c * 8);
        }
        cp_commit();
    }

    // staging map for K/V
    const int sr  = tid >> 2;            // 0..63 key row
    const int sc0 = (tid & 3) * 2;       // chunks sc0, sc0+1

    auto stage_kv = [&](int buf, int kt) {
        const uint32_t bb = KV0 + (uint32_t)buf * KVBUF_B;
        const __nv_bfloat16* skh = Khp + (size_t)(kt * BKT + sr) * HDIM;
        const __nv_bfloat16* skl = Klp + (size_t)(kt * BKT + sr) * HDIM;
        const __nv_bfloat16* svh = Vhp + (size_t)(kt * BKT + sr) * HDIM;
        const __nv_bfloat16* svl = Vlp + (size_t)(kt * BKT + sr) * HDIM;
#pragma unroll
        for (int j = 0; j < 2; j++) {
            const int c = sc0 + j;
            const uint32_t so = (uint32_t)(sr * SWF + c * 4) * 4u;
            cp16(bb + so,               skh + c * 8);
            cp16(bb + KW * 4u + so,     skl + c * 8);
            cp16(bb + 2u * KW * 4u + so, svh + c * 8);
            cp16(bb + 3u * KW * 4u + so, svl + c * 8);
        }
        cp_commit();
    };

    const int l7  = lane & 7;
    const int l15 = lane & 15;
    const int lb8 = (lane >> 3) & 1;
    const int lb16 = (lane >> 4) & 1;

    const int rloc = wid * 16 + gID;

    float m0 = -1e30f, m1 = -1e30f, l0 = 0.0f, l1 = 0.0f;
    float oacc[8][4];
#pragma unroll
    for (int nt = 0; nt < 8; nt++)
#pragma unroll
        for (int i = 0; i < 4; i++) oacc[nt][i] = 0.0f;

    const int nkt = 2 * qi + 2;

    stage_kv(0, 0);     // prefetch first tile

    for (int kt = 0; kt < nkt; kt++) {
        if (kt + 1 < nkt) {
            stage_kv((kt + 1) & 1, kt + 1);   // prefetch next
            cp_wait<1>();                     // oldest group (tile kt [+Q]) resident
        } else {
            cp_wait<0>();
        }
        __syncthreads();

        const uint32_t bb  = KV0 + (uint32_t)(kt & 1) * KVBUF_B;
        const uint32_t Kh_b = bb;
        const uint32_t Kl_b = bb + KW * 4u;
        const uint32_t Vh_b = bb + 2u * KW * 4u;
        const uint32_t Vl_b = bb + 3u * KW * 4u;

        // ---- S = Q K^T ----
        float sacc[8][4];
#pragma unroll
        for (int nt = 0; nt < 8; nt++)
#pragma unroll
            for (int i = 0; i < 4; i++) sacc[nt][i] = 0.0f;

#pragma unroll
        for (int ks = 0; ks < 4; ks++) {
            uint32_t qh[4], ql[4];
            const uint32_t qoff = (uint32_t)((rloc - gID + l15) * SWF + 8 * ks + 4 * lb16) * 4u;
            ldsm4(qh, Qh_b + qoff);
            ldsm4(ql, Ql_b + qoff);
#pragma unroll
            for (int np = 0; np < 4; np++) {
                uint32_t kh[4], kl[4];
                const uint32_t koff =
                    (uint32_t)((np * 16 + l7 + lb16 * 8) * SWF + 8 * ks + 4 * lb8) * 4u;
                ldsm4(kh, Kh_b + koff);
                ldsm4(kl, Kl_b + koff);
                mma_bf16(sacc[2 * np],     qh[0], qh[1], qh[2], qh[3], kh[0], kh[1]);
                mma_bf16(sacc[2 * np],     qh[0], qh[1], qh[2], qh[3], kl[0], kl[1]);
                mma_bf16(sacc[2 * np],     ql[0], ql[1], ql[2], ql[3], kh[0], kh[1]);
                mma_bf16(sacc[2 * np + 1], qh[0], qh[1], qh[2], qh[3], kh[2], kh[3]);
                mma_bf16(sacc[2 * np + 1], qh[0], qh[1], qh[2], qh[3], kl[2], kl[3]);
                mma_bf16(sacc[2 * np + 1], ql[0], ql[1], ql[2], ql[3], kh[2], kh[3]);
            }
        }

        // ---- Online softmax; P A-fragments in registers ----
        const bool diag = (kt >= 2 * qi);
        const float scale = 0.125f;
        uint32_t pfh[4][4], pfl[4][4];

#pragma unroll
        for (int half = 0; half < 2; half++) {
            const int rg = qbase + rloc + half * 8;
            float& m = half ? m1 : m0;
            float& l = half ? l1 : l0;

            float mx = -1e30f;
#pragma unroll
            for (int nt = 0; nt < 8; nt++) {
#pragma unroll
                for (int j = 0; j < 2; j++) {
                    float s = sacc[nt][half * 2 + j] * scale;
                    if (diag) {
                        const int cg = kt * BKT + nt * 8 + tg * 2 + j;
                        if (cg > rg) s = -1e30f;
                    }
                    sacc[nt][half * 2 + j] = s;
                    mx = fmaxf(mx, s);
                }
            }
            mx = fmaxf(mx, __shfl_xor_sync(0xffffffffu, mx, 1));
            mx = fmaxf(mx, __shfl_xor_sync(0xffffffffu, mx, 2));

            const float mn = fmaxf(m, mx);
            const float alpha = __expf(m - mn);
            float rs = 0.0f;
#pragma unroll
            for (int nt = 0; nt < 8; nt++) {
                float p0 = __expf(sacc[nt][half * 2 + 0] - mn);
                float p1 = __expf(sacc[nt][half * 2 + 1] - mn);
                rs += p0 + p1;
                __nv_bfloat16 h0, lo0, h1, lo1;
                split_bf(p0, h0, lo0);
                split_bf(p1, h1, lo1);
                const int ks   = nt >> 1;
                const int slot = (nt & 1) * 2 + half;
                pfh[ks][slot] = pack2(h0, h1);
                pfl[ks][slot] = pack2(lo0, lo1);
            }
            rs += __shfl_xor_sync(0xffffffffu, rs, 1);
            rs += __shfl_xor_sync(0xffffffffu, rs, 2);
            l = l * alpha + rs;
            m = mn;
#pragma unroll
            for (int nt = 0; nt < 8; nt++) {
                oacc[nt][half * 2 + 0] *= alpha;
                oacc[nt][half * 2 + 1] *= alpha;
            }
        }

        // ---- O += P V ----
#pragma unroll
        for (int ks = 0; ks < 4; ks++) {
#pragma unroll
            for (int np = 0; np < 4; np++) {
                uint32_t vh[4], vl[4];
                const uint32_t voff =
                    (uint32_t)((ks * 16 + l7 + lb8 * 8) * SWF + 8 * np + 4 * lb16) * 4u;
                ldsm4t(vh, Vh_b + voff);
                ldsm4t(vl, Vl_b + voff);
                mma_bf16(oacc[2 * np],     pfh[ks][0], pfh[ks][1], pfh[ks][2], pfh[ks][3], vh[0], vh[1]);
                mma_bf16(oacc[2 * np],     pfh[ks][0], pfh[ks][1], pfh[ks][2], pfh[ks][3], vl[0], vl[1]);
                mma_bf16(oacc[2 * np],     pfl[ks][0], pfl[ks][1], pfl[ks][2], pfl[ks][3], vh[0], vh[1]);
                mma_bf16(oacc[2 * np + 1], pfh[ks][0], pfh[ks][1], pfh[ks][2], pfh[ks][3], vh[2], vh[3]);
                mma_bf16(oacc[2 * np + 1], pfh[ks][0], pfh[ks][1], pfh[ks][2], pfh[ks][3], vl[2], vl[3]);
                mma_bf16(oacc[2 * np + 1], pfl[ks][0], pfl[ks][1], pfl[ks][2], pfl[ks][3], vh[2], vh[3]);
            }
        }
        __syncthreads();   // protect buffer (kt+1)&1 before next prefetch overwrites
    }

    // ---- Epilogue ----
    const float inv0 = 1.0f / l0;
    const float inv1 = 1.0f / l1;
#pragma unroll
    for (int half = 0; half < 2; half++) {
        const float inv = half ? inv1 : inv0;
        const int rg = qbase + rloc + half * 8;
        const size_t rowo = ((size_t)b * SEQ + rg) * DMODEL + h * HDIM;
#pragma unroll
        for (int nt = 0; nt < 8; nt++) {
            float v0 = oacc[nt][half * 2 + 0] * inv;
            float v1 = oacc[nt][half * 2 + 1] * inv;
            __nv_bfloat16 h0, lo0, h1, lo1;
            split_bf(v0, h0, lo0);
            split_bf(v1, h1, lo1);
            const size_t o = rowo + nt * 8 + tg * 2;
            *(uint32_t*)(g_ctxh + o) = pack2(h0, h1);
            *(uint32_t*)(g_ctxl + o) = pack2(lo0, lo1);
        }
    }
}

// ---------------------------------------------------------------------------
extern "C" void kernel_launch(void* const* d_in, const int* in_sizes, int n_in,
                              void* d_out, int out_size)
{
    const float* x  = (const float*)d_in[0];
    const float* Wq = (const float*)d_in[1];
    const float* Wk = (const float*)d_in[2];
    const float* Wv = (const float*)d_in[3];
    const float* Wo = (const float*)d_in[4];
    float* out = (float*)d_out;

    const int gsmem = GSMEM_W * 4;     // 81920 B
    const int fsmem = FSMEM_W * 4;     // 110592 B

    cudaFuncSetAttribute(gemm_bf<1>,
                         cudaFuncAttributeMaxDynamicSharedMemorySize, gsmem);
    cudaFuncSetAttribute(gemm_bf<0>,
                         cudaFuncAttributeMaxDynamicSharedMemorySize, gsmem);
    cudaFuncSetAttribute(flash_bf,
                         cudaFuncAttributeMaxDynamicSharedMemorySize, fsmem);

    __nv_bfloat16 *xh, *xl;
    cudaGetSymbolAddress((void**)&xh, g_xh);
    cudaGetSymbolAddress((void**)&xl, g_xl);

    const int nx = ROWS * DMODEL;
    const int nw = DMODEL * DMODEL;
    split_kernel<<<(nx / 4 + 255) / 256, 256>>>(x, xh, xl, nx);
    dim3 gs((nw / 4 + 255) / 256, 4);
    split4_kernel<<<gs, 256>>>(Wq, Wk, Wv, Wo);

    // 1) QKV projections
    dim3 g1(DMODEL / 128, ROWS / 128, 3);
    gemm_bf<1><<<g1, 256, gsmem>>>(nullptr);

    // 2) Causal flash attention
    dim3 g2(SEQ / BQ, BHEADS);
    flash_bf<<<g2, 256, fsmem>>>();

    // 3) Output projection
    dim3 g3(DMODEL / 128, ROWS / 128, 1);
    gemm_bf<0><<<g3, 256, gsmem>>>(out);
}

// round 12
// speedup vs baseline: 2.7022x; 1.0373x over previous
#include <cuda_runtime.h>
#include <cuda_bf16.h>
#include <cstdint>

#define BATCH   4
#define SEQ     2048
#define DMODEL  1024
#define NHEADS  16
#define HDIM    64
#define BHEADS  (BATCH * NHEADS)        // 64
#define ROWS    (BATCH * SEQ)           // 8192

// ---------------------------------------------------------------------------
// Device-global scratch (bf16 hi/lo planes)
// ---------------------------------------------------------------------------
__device__ __nv_bfloat16 g_xh[(size_t)ROWS * DMODEL];
__device__ __nv_bfloat16 g_xl[(size_t)ROWS * DMODEL];
__device__ __nv_bfloat16 g_wh[4u * DMODEL * DMODEL];   // q,k,v,o  (n x k row-major)
__device__ __nv_bfloat16 g_wl[4u * DMODEL * DMODEL];
__device__ __nv_bfloat16 g_qkvh[3u * BHEADS * SEQ * HDIM];  // [which][bh][s][e]
__device__ __nv_bfloat16 g_qkvl[3u * BHEADS * SEQ * HDIM];
__device__ __nv_bfloat16 g_ctxh[(size_t)ROWS * DMODEL];
__device__ __nv_bfloat16 g_ctxl[(size_t)ROWS * DMODEL];

// ---------------------------------------------------------------------------
// Helpers
// ---------------------------------------------------------------------------
__device__ __forceinline__ void mma_bf16(float* c,
                                         uint32_t a0, uint32_t a1, uint32_t a2, uint32_t a3,
                                         uint32_t b0, uint32_t b1) {
    asm volatile(
        "mma.sync.aligned.m16n8k16.row.col.f32.bf16.bf16.f32 "
        "{%0,%1,%2,%3}, {%4,%5,%6,%7}, {%8,%9}, {%0,%1,%2,%3};\n"
        : "+f"(c[0]), "+f"(c[1]), "+f"(c[2]), "+f"(c[3])
        : "r"(a0), "r"(a1), "r"(a2), "r"(a3), "r"(b0), "r"(b1));
}

__device__ __forceinline__ void ldsm4(uint32_t* r, uint32_t addr) {
    asm volatile("ldmatrix.sync.aligned.m8n8.x4.shared.b16 {%0,%1,%2,%3}, [%4];"
                 : "=r"(r[0]), "=r"(r[1]), "=r"(r[2]), "=r"(r[3]) : "r"(addr));
}
__device__ __forceinline__ void ldsm4t(uint32_t* r, uint32_t addr) {
    asm volatile("ldmatrix.sync.aligned.m8n8.x4.trans.shared.b16 {%0,%1,%2,%3}, [%4];"
                 : "=r"(r[0]), "=r"(r[1]), "=r"(r[2]), "=r"(r[3]) : "r"(addr));
}

__device__ __forceinline__ void cp16(uint32_t smem_dst, const void* gmem_src) {
    asm volatile("cp.async.cg.shared.global [%0], [%1], 16;\n"
                 :: "r"(smem_dst), "l"(gmem_src));
}
__device__ __forceinline__ void cp_commit() {
    asm volatile("cp.async.commit_group;\n");
}
template <int N>
__device__ __forceinline__ void cp_wait() {
    asm volatile("cp.async.wait_group %0;\n" :: "n"(N));
}

__device__ __forceinline__ void split_bf(float x, __nv_bfloat16& h, __nv_bfloat16& l) {
    h = __float2bfloat16(x);
    l = __float2bfloat16(x - __bfloat162float(h));
}
__device__ __forceinline__ uint32_t pack2(__nv_bfloat16 a, __nv_bfloat16 b) {
    return (uint32_t)__bfloat16_as_ushort(a) | ((uint32_t)__bfloat16_as_ushort(b) << 16);
}
__device__ __forceinline__ float exp2a(float x) {
    float r;
    asm("ex2.approx.ftz.f32 %0, %1;" : "=f"(r) : "f"(x));
    return r;
}

// ---------------------------------------------------------------------------
// Pre-split kernels
// ---------------------------------------------------------------------------
__global__ void split_kernel(const float* __restrict__ src,
                             __nv_bfloat16* __restrict__ hi,
                             __nv_bfloat16* __restrict__ lo, int n)
{
    int i = (blockIdx.x * blockDim.x + threadIdx.x) * 4;
    if (i >= n) return;
    float4 v = *(const float4*)(src + i);
    __nv_bfloat16 h0, l0, h1, l1, h2, l2, h3, l3;
    split_bf(v.x, h0, l0); split_bf(v.y, h1, l1);
    split_bf(v.z, h2, l2); split_bf(v.w, h3, l3);
    *(uint32_t*)(hi + i)     = pack2(h0, h1);
    *(uint32_t*)(hi + i + 2) = pack2(h2, h3);
    *(uint32_t*)(lo + i)     = pack2(l0, l1);
    *(uint32_t*)(lo + i + 2) = pack2(l2, l3);
}

__global__ void split4_kernel(const float* __restrict__ W0, const float* __restrict__ W1,
                              const float* __restrict__ W2, const float* __restrict__ W3)
{
    const int z = blockIdx.y;
    const float* src = (z == 0) ? W0 : (z == 1) ? W1 : (z == 2) ? W2 : W3;
    const size_t nw = (size_t)DMODEL * DMODEL;
    __nv_bfloat16* hi = g_wh + z * nw;
    __nv_bfloat16* lo = g_wl + z * nw;
    int i = (blockIdx.x * blockDim.x + threadIdx.x) * 4;
    if (i >= (int)nw) return;
    float4 v = *(const float4*)(src + i);
    __nv_bfloat16 h0, l0, h1, l1, h2, l2, h3, l3;
    split_bf(v.x, h0, l0); split_bf(v.y, h1, l1);
    split_bf(v.z, h2, l2); split_bf(v.w, h3, l3);
    *(uint32_t*)(hi + i)     = pack2(h0, h1);
    *(uint32_t*)(hi + i + 2) = pack2(h2, h3);
    *(uint32_t*)(lo + i)     = pack2(l0, l1);
    *(uint32_t*)(lo + i + 2) = pack2(l2, l3);
}

// ---------------------------------------------------------------------------
// bf16x3 GEMM, ldmatrix fragments, single-sync pipeline, spread mma order.
// ---------------------------------------------------------------------------
#define SWG     20
#define PLANEW  (128 * SWG)
#define GSMEM_W (2 * 4 * PLANEW)

template <int MODE>
__global__ __launch_bounds__(256, 2)
void gemm_bf(float* __restrict__ Cout)
{
    extern __shared__ uint32_t smw[];

    const __nv_bfloat16 *Ah, *Al, *Bh, *Bl;
    if (MODE == 1) {
        Ah = g_xh;  Al = g_xl;
        const size_t wo = (size_t)blockIdx.z * DMODEL * DMODEL;
        Bh = g_wh + wo;  Bl = g_wl + wo;
    } else {
        Ah = g_ctxh;  Al = g_ctxl;
        Bh = g_wh + 3u * DMODEL * DMODEL;  Bl = g_wl + 3u * DMODEL * DMODEL;
    }

    const int tid  = threadIdx.x;
    const int lane = tid & 31;
    const int wid  = tid >> 5;
    const int wm   = wid >> 1;
    const int wn   = wid & 1;
    const int gID  = lane >> 2;
    const int tg   = lane & 3;

    const int l7   = lane & 7;
    const int l15  = lane & 15;
    const int lb8  = (lane >> 3) & 1;
    const int lb16 = (lane >> 4) & 1;

    const int brow = blockIdx.y * 128;
    const int bcol = blockIdx.x * 128;

    const int srow = tid >> 1;
    const int cb   = (tid & 1) * 2;

    const uint32_t smem0 = (uint32_t)__cvta_generic_to_shared(smw);

    auto stage = [&](int buf, int k0) {
        const uint32_t base = smem0 + (uint32_t)(buf * 4 * PLANEW) * 4u;
        const __nv_bfloat16* gsrc[4] = {
            Ah + (size_t)(brow + srow) * DMODEL + k0,
            Al + (size_t)(brow + srow) * DMODEL + k0,
            Bh + (size_t)(bcol + srow) * DMODEL + k0,
            Bl + (size_t)(bcol + srow) * DMODEL + k0 };
#pragma unroll
        for (int p = 0; p < 4; p++) {
#pragma unroll
            for (int j = 0; j < 2; j++) {
                const int c = cb + j;
                cp16(base + (uint32_t)(p * PLANEW + srow * SWG + c * 4) * 4u,
                     gsrc[p] + c * 8);
            }
        }
        cp_commit();
    };

    float acc[2][8][4];
#pragma unroll
    for (int mt = 0; mt < 2; mt++)
#pragma unroll
        for (int nt = 0; nt < 8; nt++)
#pragma unroll
            for (int i = 0; i < 4; i++) acc[mt][nt][i] = 0.0f;

    stage(0, 0);

    for (int kt = 0; kt < DMODEL / 32; kt++) {
        cp_wait<0>();          // tile kt resident (issued last iteration)
        __syncthreads();       // publish tile kt; everyone done with buf (kt+1)&1

        if (kt + 1 < DMODEL / 32)
            stage((kt + 1) & 1, (kt + 1) * 32);   // overlaps compute below

        const uint32_t bufw = (uint32_t)((kt & 1) * 4 * PLANEW) * 4u;
        const uint32_t Ah_b = smem0 + bufw;
        const uint32_t Al_b = Ah_b + PLANEW * 4u;
        const uint32_t Bh_b = Al_b + PLANEW * 4u;
        const uint32_t Bl_b = Bh_b + PLANEW * 4u;

#pragma unroll
        for (int ks = 0; ks < 2; ks++) {
            const int wb = ks * 8;

            uint32_t ah[2][4], al[2][4];
#pragma unroll
            for (int mt = 0; mt < 2; mt++) {
                const uint32_t aoff =
                    (uint32_t)((wm * 32 + mt * 16 + l15) * SWG + wb + 4 * lb16) * 4u;
                ldsm4(ah[mt], Ah_b + aoff);
                ldsm4(al[mt], Al_b + aoff);
            }

#pragma unroll
            for (int np = 0; np < 4; np++) {
                uint32_t bhf[4], blf[4];
                const uint32_t boff =
                    (uint32_t)((wn * 64 + np * 16 + l7 + lb16 * 8) * SWG + wb + 4 * lb8) * 4u;
                ldsm4(bhf, Bh_b + boff);
                ldsm4(blf, Bl_b + boff);
                // product-major order: same-acc mmas separated by 3 others
#pragma unroll
                for (int half = 0; half < 2; half++) {
                    const int nt = 2 * np + half;
#pragma unroll
                    for (int mt = 0; mt < 2; mt++)
                        mma_bf16(acc[mt][nt], ah[mt][0], ah[mt][1], ah[mt][2], ah[mt][3],
                                 bhf[2 * half], bhf[2 * half + 1]);
                }
#pragma unroll
                for (int half = 0; half < 2; half++) {
                    const int nt = 2 * np + half;
#pragma unroll
                    for (int mt = 0; mt < 2; mt++)
                        mma_bf16(acc[mt][nt], ah[mt][0], ah[mt][1], ah[mt][2], ah[mt][3],
                                 blf[2 * half], blf[2 * half + 1]);
                }
#pragma unroll
                for (int half = 0; half < 2; half++) {
                    const int nt = 2 * np + half;
#pragma unroll
                    for (int mt = 0; mt < 2; mt++)
                        mma_bf16(acc[mt][nt], al[mt][0], al[mt][1], al[mt][2], al[mt][3],
                                 bhf[2 * half], bhf[2 * half + 1]);
                }
            }
        }
    }

    if (MODE == 1) {
        const size_t zo = (size_t)blockIdx.z * (BHEADS * SEQ * HDIM);
#pragma unroll
        for (int mt = 0; mt < 2; mt++) {
            const int rbase = brow + wm * 32 + mt * 16 + gID;
#pragma unroll
            for (int nt = 0; nt < 8; nt++) {
                const int col = bcol + wn * 64 + nt * 8 + tg * 2;
                const int h = col >> 6;
                const int e = col & 63;
#pragma unroll
                for (int half = 0; half < 2; half++) {
                    const int r = rbase + half * 8;
                    const int b = r >> 11;
                    const int s = r & (SEQ - 1);
                    const size_t o = zo + ((size_t)(b * NHEADS + h) * SEQ + s) * HDIM + e;
                    __nv_bfloat16 h0, l0, h1, l1;
                    split_bf(acc[mt][nt][half * 2 + 0], h0, l0);
                    split_bf(acc[mt][nt][half * 2 + 1], h1, l1);
                    *(uint32_t*)(g_qkvh + o) = pack2(h0, h1);
                    *(uint32_t*)(g_qkvl + o) = pack2(l0, l1);
                }
            }
        }
    } else {
#pragma unroll
        for (int mt = 0; mt < 2; mt++) {
            const int rbase = brow + wm * 32 + mt * 16 + gID;
#pragma unroll
            for (int nt = 0; nt < 8; nt++) {
                const int col = bcol + wn * 64 + nt * 8 + tg * 2;
#pragma unroll
                for (int half = 0; half < 2; half++) {
                    const int r = rbase + half * 8;
                    float2 v = make_float2(acc[mt][nt][half * 2], acc[mt][nt][half * 2 + 1]);
                    *(float2*)(Cout + (size_t)r * DMODEL + col) = v;
                }
            }
        }
    }
}

// ---------------------------------------------------------------------------
// bf16x3 flash attention (causal) — single-sync pipeline, spread mma order,
// exp2-folded softmax. Double-buffered K/V.
// ---------------------------------------------------------------------------
#define BQ   128
#define BKT  64
#define SWF  36
#define QW   (BQ * SWF)
#define KW   (BKT * SWF)
#define KVBUF_B (4u * KW * 4u)
#define FSMEM_W (2*QW + 8*KW)        // 110592 B

__global__ __launch_bounds__(256, 2)
void flash_bf()
{
    extern __shared__ uint32_t smw[];

    const int tid  = threadIdx.x;
    const int lane = tid & 31;
    const int wid  = tid >> 5;
    const int gID  = lane >> 2;
    const int tg   = lane & 3;

    const int bh    = blockIdx.y;
    const int b     = bh >> 4;
    const int h     = bh & 15;
    const int qi    = (int)gridDim.x - 1 - (int)blockIdx.x;
    const int qbase = qi * BQ;

    const __nv_bfloat16* Qhp = g_qkvh + (size_t)bh * (SEQ * HDIM);
    const __nv_bfloat16* Qlp = g_qkvl + (size_t)bh * (SEQ * HDIM);
    const __nv_bfloat16* Khp = g_qkvh + (size_t)(BHEADS + bh) * (SEQ * HDIM);
    const __nv_bfloat16* Klp = g_qkvl + (size_t)(BHEADS + bh) * (SEQ * HDIM);
    const __nv_bfloat16* Vhp = g_qkvh + (size_t)(2 * BHEADS + bh) * (SEQ * HDIM);
    const __nv_bfloat16* Vlp = g_qkvl + (size_t)(2 * BHEADS + bh) * (SEQ * HDIM);

    const uint32_t smem0 = (uint32_t)__cvta_generic_to_shared(smw);
    const uint32_t Qh_b = smem0;
    const uint32_t Ql_b = Qh_b + QW * 4u;
    const uint32_t KV0  = Ql_b + QW * 4u;

    // ---- Q staging (once) ----
    {
        const int r  = tid >> 1;
        const int c0 = (tid & 1) * 4;
        const __nv_bfloat16* sh = Qhp + (size_t)(qbase + r) * HDIM;
        const __nv_bfloat16* sl = Qlp + (size_t)(qbase + r) * HDIM;
#pragma unroll
        for (int j = 0; j < 4; j++) {
            const int c = c0 + j;
            cp16(Qh_b + (uint32_t)(r * SWF + c * 4) * 4u, sh + c * 8);
            cp16(Ql_b + (uint32_t)(r * SWF + c * 4) * 4u, sl + c * 8);
        }
        cp_commit();
    }

    const int sr  = tid >> 2;
    const int sc0 = (tid & 3) * 2;

    auto stage_kv = [&](int buf, int kt) {
        const uint32_t bb = KV0 + (uint32_t)buf * KVBUF_B;
        const __nv_bfloat16* skh = Khp + (size_t)(kt * BKT + sr) * HDIM;
        const __nv_bfloat16* skl = Klp + (size_t)(kt * BKT + sr) * HDIM;
        const __nv_bfloat16* svh = Vhp + (size_t)(kt * BKT + sr) * HDIM;
        const __nv_bfloat16* svl = Vlp + (size_t)(kt * BKT + sr) * HDIM;
#pragma unroll
        for (int j = 0; j < 2; j++) {
            const int c = sc0 + j;
            const uint32_t so = (uint32_t)(sr * SWF + c * 4) * 4u;
            cp16(bb + so,                skh + c * 8);
            cp16(bb + KW * 4u + so,      skl + c * 8);
            cp16(bb + 2u * KW * 4u + so, svh + c * 8);
            cp16(bb + 3u * KW * 4u + so, svl + c * 8);
        }
        cp_commit();
    };

    const int l7  = lane & 7;
    const int l15 = lane & 15;
    const int lb8 = (lane >> 3) & 1;
    const int lb16 = (lane >> 4) & 1;

    const int rloc = wid * 16 + gID;

    float m0 = -1e30f, m1 = -1e30f, l0 = 0.0f, l1 = 0.0f;
    float oacc[8][4];
#pragma unroll
    for (int nt = 0; nt < 8; nt++)
#pragma unroll
        for (int i = 0; i < 4; i++) oacc[nt][i] = 0.0f;

    const int nkt = 2 * qi + 2;
    const float scale2 = 0.125f * 1.44269504f;   // 1/sqrt(64) * log2(e)

    stage_kv(0, 0);

    for (int kt = 0; kt < nkt; kt++) {
        cp_wait<0>();      // tile kt (and Q on first iter) resident
        __syncthreads();   // publish; everyone done reading buf (kt+1)&1

        if (kt + 1 < nkt)
            stage_kv((kt + 1) & 1, kt + 1);   // overlaps compute below

        const uint32_t bb  = KV0 + (uint32_t)(kt & 1) * KVBUF_B;
        const uint32_t Kh_b = bb;
        const uint32_t Kl_b = bb + KW * 4u;
        const uint32_t Vh_b = bb + 2u * KW * 4u;
        const uint32_t Vl_b = bb + 3u * KW * 4u;

        // ---- S = Q K^T ----
        float sacc[8][4];
#pragma unroll
        for (int nt = 0; nt < 8; nt++)
#pragma unroll
            for (int i = 0; i < 4; i++) sacc[nt][i] = 0.0f;

#pragma unroll
        for (int ks = 0; ks < 4; ks++) {
            uint32_t qh[4], ql[4];
            const uint32_t qoff = (uint32_t)((rloc - gID + l15) * SWF + 8 * ks + 4 * lb16) * 4u;
            ldsm4(qh, Qh_b + qoff);
            ldsm4(ql, Ql_b + qoff);
#pragma unroll
            for (int np = 0; np < 4; np++) {
                uint32_t kh[4], kl[4];
                const uint32_t koff =
                    (uint32_t)((np * 16 + l7 + lb16 * 8) * SWF + 8 * ks + 4 * lb8) * 4u;
                ldsm4(kh, Kh_b + koff);
                ldsm4(kl, Kl_b + koff);
                // product-major: same-acc pairs separated
                mma_bf16(sacc[2 * np],     qh[0], qh[1], qh[2], qh[3], kh[0], kh[1]);
                mma_bf16(sacc[2 * np + 1], qh[0], qh[1], qh[2], qh[3], kh[2], kh[3]);
                mma_bf16(sacc[2 * np],     qh[0], qh[1], qh[2], qh[3], kl[0], kl[1]);
                mma_bf16(sacc[2 * np + 1], qh[0], qh[1], qh[2], qh[3], kl[2], kl[3]);
                mma_bf16(sacc[2 * np],     ql[0], ql[1], ql[2], ql[3], kh[0], kh[1]);
                mma_bf16(sacc[2 * np + 1], ql[0], ql[1], ql[2], ql[3], kh[2], kh[3]);
            }
        }

        // ---- Online softmax (base-2 domain); P A-fragments in registers ----
        const bool diag = (kt >= 2 * qi);
        uint32_t pfh[4][4], pfl[4][4];

#pragma unroll
        for (int half = 0; half < 2; half++) {
            const int rg = qbase + rloc + half * 8;
            float& m = half ? m1 : m0;
            float& l = half ? l1 : l0;

            float mx = -1e30f;
#pragma unroll
            for (int nt = 0; nt < 8; nt++) {
#pragma unroll
                for (int j = 0; j < 2; j++) {
                    float s = sacc[nt][half * 2 + j] * scale2;
                    if (diag) {
                        const int cg = kt * BKT + nt * 8 + tg * 2 + j;
                        if (cg > rg) s = -1e30f;
                    }
                    sacc[nt][half * 2 + j] = s;
                    mx = fmaxf(mx, s);
                }
            }
            mx = fmaxf(mx, __shfl_xor_sync(0xffffffffu, mx, 1));
            mx = fmaxf(mx, __shfl_xor_sync(0xffffffffu, mx, 2));

            const float mn = fmaxf(m, mx);
            const float alpha = exp2a(m - mn);
            float rs = 0.0f;
#pragma unroll
            for (int nt = 0; nt < 8; nt++) {
                float p0 = exp2a(sacc[nt][half * 2 + 0] - mn);
                float p1 = exp2a(sacc[nt][half * 2 + 1] - mn);
                rs += p0 + p1;
                __nv_bfloat16 h0, lo0, h1, lo1;
                split_bf(p0, h0, lo0);
                split_bf(p1, h1, lo1);
                const int ks   = nt >> 1;
                const int slot = (nt & 1) * 2 + half;
                pfh[ks][slot] = pack2(h0, h1);
                pfl[ks][slot] = pack2(lo0, lo1);
            }
            rs += __shfl_xor_sync(0xffffffffu, rs, 1);
            rs += __shfl_xor_sync(0xffffffffu, rs, 2);
            l = l * alpha + rs;
            m = mn;
#pragma unroll
            for (int nt = 0; nt < 8; nt++) {
                oacc[nt][half * 2 + 0] *= alpha;
                oacc[nt][half * 2 + 1] *= alpha;
            }
        }

        // ---- O += P V ----
#pragma unroll
        for (int ks = 0; ks < 4; ks++) {
#pragma unroll
            for (int np = 0; np < 4; np++) {
                uint32_t vh[4], vl[4];
                const uint32_t voff =
                    (uint32_t)((ks * 16 + l7 + lb8 * 8) * SWF + 8 * np + 4 * lb16) * 4u;
                ldsm4t(vh, Vh_b + voff);
                ldsm4t(vl, Vl_b + voff);
                // product-major: same-acc pairs separated
                mma_bf16(oacc[2 * np],     pfh[ks][0], pfh[ks][1], pfh[ks][2], pfh[ks][3], vh[0], vh[1]);
                mma_bf16(oacc[2 * np + 1], pfh[ks][0], pfh[ks][1], pfh[ks][2], pfh[ks][3], vh[2], vh[3]);
                mma_bf16(oacc[2 * np],     pfh[ks][0], pfh[ks][1], pfh[ks][2], pfh[ks][3], vl[0], vl[1]);
                mma_bf16(oacc[2 * np + 1], pfh[ks][0], pfh[ks][1], pfh[ks][2], pfh[ks][3], vl[2], vl[3]);
                mma_bf16(oacc[2 * np],     pfl[ks][0], pfl[ks][1], pfl[ks][2], pfl[ks][3], vh[0], vh[1]);
                mma_bf16(oacc[2 * np + 1], pfl[ks][0], pfl[ks][1], pfl[ks][2], pfl[ks][3], vh[2], vh[3]);
            }
        }
    }

    // ---- Epilogue ----
    const float inv0 = 1.0f / l0;
    const float inv1 = 1.0f / l1;
#pragma unroll
    for (int half = 0; half < 2; half++) {
        const float inv = half ? inv1 : inv0;
        const int rg = qbase + rloc + half * 8;
        const size_t rowo = ((size_t)b * SEQ + rg) * DMODEL + h * HDIM;
#pragma unroll
        for (int nt = 0; nt < 8; nt++) {
            float v0 = oacc[nt][half * 2 + 0] * inv;
            float v1 = oacc[nt][half * 2 + 1] * inv;
            __nv_bfloat16 h0, lo0, h1, lo1;
            split_bf(v0, h0, lo0);
            split_bf(v1, h1, lo1);
            const size_t o = rowo + nt * 8 + tg * 2;
            *(uint32_t*)(g_ctxh + o) = pack2(h0, h1);
            *(uint32_t*)(g_ctxl + o) = pack2(lo0, lo1);
        }
    }
}

// ---------------------------------------------------------------------------
extern "C" void kernel_launch(void* const* d_in, const int* in_sizes, int n_in,
                              void* d_out, int out_size)
{
    const float* x  = (const float*)d_in[0];
    const float* Wq = (const float*)d_in[1];
    const float* Wk = (const float*)d_in[2];
    const float* Wv = (const float*)d_in[3];
    const float* Wo = (const float*)d_in[4];
    float* out = (float*)d_out;

    const int gsmem = GSMEM_W * 4;     // 81920 B
    const int fsmem = FSMEM_W * 4;     // 110592 B

    cudaFuncSetAttribute(gemm_bf<1>,
                         cudaFuncAttributeMaxDynamicSharedMemorySize, gsmem);
    cudaFuncSetAttribute(gemm_bf<0>,
                         cudaFuncAttributeMaxDynamicSharedMemorySize, gsmem);
    cudaFuncSetAttribute(flash_bf,
                         cudaFuncAttributeMaxDynamicSharedMemorySize, fsmem);

    __nv_bfloat16 *xh, *xl;
    cudaGetSymbolAddress((void**)&xh, g_xh);
    cudaGetSymbolAddress((void**)&xl, g_xl);

    const int nx = ROWS * DMODEL;
    const int nw = DMODEL * DMODEL;
    split_kernel<<<(nx / 4 + 255) / 256, 256>>>(x, xh, xl, nx);
    dim3 gs((nw / 4 + 255) / 256, 4);
    split4_kernel<<<gs, 256>>>(Wq, Wk, Wv, Wo);

    // 1) QKV projections
    dim3 g1(DMODEL / 128, ROWS / 128, 3);
    gemm_bf<1><<<g1, 256, gsmem>>>(nullptr);

    // 2) Causal flash attention
    dim3 g2(SEQ / BQ, BHEADS);
    flash_bf<<<g2, 256, fsmem>>>();

    // 3) Output projection
    dim3 g3(DMODEL / 128, ROWS / 128, 1);
    gemm_bf<0><<<g3, 256, gsmem>>>(out);
}